// round 1
// baseline (speedup 1.0000x reference)
#include <cuda_runtime.h>
#include <cuda_bf16.h>
#include <math.h>

#define NMAX 50000
#define EMAX 800000
#define DDIM 128

// ---------------- device scratch (no allocations allowed) ----------------
__device__ float g_emb [NMAX * DDIM];
__device__ float g_emb2[NMAX * DDIM];
__device__ float g_Q   [NMAX * DDIM];
__device__ float g_K   [NMAX * DDIM];
__device__ float g_V   [NMAX * DDIM];
__device__ int   g_deg [NMAX];
__device__ int   g_cur [NMAX];
__device__ int   g_off [NMAX + 1];
__device__ int   g_col [EMAX];
__device__ int   g_hiOr;

// ---------------- misc small kernels ----------------
__global__ void zero_kernel(int* deg, int* cur, int* hiOr, int n)
{
    int i = blockIdx.x * blockDim.x + threadIdx.x;
    if (i < n) { deg[i] = 0; cur[i] = 0; }
    if (i == 0) *hiOr = 0;
}

// Probe edge_index dtype: int64 values < 2^31 have zero high 32-bit words.
__global__ void detect_kernel(const unsigned int* __restrict__ p, int E, int* hiOr)
{
    int i = blockIdx.x * blockDim.x + threadIdx.x;
    int S = (E < 4096) ? E : 4096;
    if (i < S) {
        if (p[2 * i + 1] != 0u) atomicOr(hiOr, 1);
    }
}

__device__ __forceinline__ int eidx_at(const void* p, int i, bool i64)
{
    if (i64) return (int)(((const long long*)p)[i]);
    return ((const int*)p)[i];
}

__global__ void hist_kernel(const void* __restrict__ ei, int E, int n,
                            int* __restrict__ deg, const int* __restrict__ hiOr)
{
    bool i64 = (*hiOr == 0);
    int e = blockIdx.x * blockDim.x + threadIdx.x;
    if (e < E) {
        int r = eidx_at(ei, e, i64);
        if ((unsigned)r < (unsigned)n) atomicAdd(&deg[r], 1);
    }
}

// Single-block exclusive scan over n<=50000 counts (warp-shuffle based).
__global__ void scan_kernel(const int* __restrict__ deg, int* __restrict__ off, int n)
{
    __shared__ int warpTot[32];
    const int tid = threadIdx.x;
    const int lane = tid & 31, wid = tid >> 5;
    int carry = 0;
    for (int base = 0; base < n; base += 1024) {
        int i = base + tid;
        int v = (i < n) ? deg[i] : 0;
        int x = v;
        #pragma unroll
        for (int o = 1; o < 32; o <<= 1) {
            int t = __shfl_up_sync(0xffffffffu, x, o);
            if (lane >= o) x += t;
        }
        if (lane == 31) warpTot[wid] = x;
        __syncthreads();
        if (wid == 0) {
            int y = warpTot[lane];
            #pragma unroll
            for (int o = 1; o < 32; o <<= 1) {
                int t = __shfl_up_sync(0xffffffffu, y, o);
                if (lane >= o) y += t;
            }
            warpTot[lane] = y;
        }
        __syncthreads();
        int warpPrefix = (wid == 0) ? 0 : warpTot[wid - 1];
        int incl = warpPrefix + x;
        if (i < n) off[i] = carry + incl - v;    // exclusive prefix
        carry += warpTot[31];
        __syncthreads();
    }
    if (tid == 0) off[n] = carry;
}

__global__ void scatter_kernel(const void* __restrict__ ei, int E, int n,
                               const int* __restrict__ off, int* __restrict__ cur,
                               int* __restrict__ col, const int* __restrict__ hiOr)
{
    bool i64 = (*hiOr == 0);
    int e = blockIdx.x * blockDim.x + threadIdx.x;
    if (e < E) {
        int r = eidx_at(ei, e, i64);
        int c = eidx_at(ei, E + e, i64);
        if ((unsigned)r < (unsigned)n) {
            int pos = off[r] + atomicAdd(&cur[r], 1);
            if ((unsigned)c >= (unsigned)n) c = 0;
            col[pos] = c;
        }
    }
}

// ---------------- fp32 tiled GEMM: C[n,M] = A[n,K] @ W[K,M] (+b1 +b2) -----
template <int K, int M>
__launch_bounds__(256)
__global__ void gemm_kernel(const float* __restrict__ A, const float* __restrict__ W,
                            const float* __restrict__ b1, const float* __restrict__ b2,
                            float* __restrict__ C, int n)
{
    constexpr int KC = 32;
    constexpr int MC = M / 32;
    __shared__ float As[64][KC + 1];
    __shared__ float Ws[KC][M];
    const int tid = threadIdx.x;
    const int tr = tid >> 5;       // 0..7
    const int tc = tid & 31;       // 0..31
    const int rowBase = blockIdx.x * 64;

    float acc[8][MC];
    #pragma unroll
    for (int i = 0; i < 8; i++)
        #pragma unroll
        for (int j = 0; j < MC; j++) acc[i][j] = 0.f;

    for (int k0 = 0; k0 < K; k0 += KC) {
        #pragma unroll
        for (int i = tid; i < 64 * KC; i += 256) {
            int r = i >> 5;
            int kk = i & 31;
            int gr = rowBase + r;
            As[r][kk] = (gr < n) ? A[gr * K + k0 + kk] : 0.f;
        }
        #pragma unroll
        for (int i = tid; i < KC * M; i += 256) {
            int kk = i / M;
            int m = i - kk * M;
            Ws[kk][m] = W[(k0 + kk) * M + m];
        }
        __syncthreads();
        #pragma unroll
        for (int kk = 0; kk < KC; kk++) {
            float a[8];
            #pragma unroll
            for (int i = 0; i < 8; i++) a[i] = As[tr + 8 * i][kk];
            #pragma unroll
            for (int j = 0; j < MC; j++) {
                float w = Ws[kk][tc + 32 * j];
                #pragma unroll
                for (int i = 0; i < 8; i++) acc[i][j] = fmaf(a[i], w, acc[i][j]);
            }
        }
        __syncthreads();
    }

    #pragma unroll
    for (int i = 0; i < 8; i++) {
        int gr = rowBase + tr + 8 * i;
        if (gr < n) {
            #pragma unroll
            for (int j = 0; j < MC; j++) {
                int m = tc + 32 * j;
                float b = 0.f;
                if (b1) b += b1[m];
                if (b2) b += b2[m];
                C[gr * M + m] = acc[i][j] + b;
            }
        }
    }
}

// ---------------- warp-per-node: attention agg + residual + LayerNorm ----
__launch_bounds__(256)
__global__ void agg_ln_kernel(const float* __restrict__ Q, const float* __restrict__ Km,
                              const float* __restrict__ V, const float* __restrict__ emb,
                              const int* __restrict__ off, const int* __restrict__ colArr,
                              const float* __restrict__ lns, const float* __restrict__ lnb,
                              float* __restrict__ outp, int n)
{
    int gw = (blockIdx.x * blockDim.x + threadIdx.x) >> 5;   // node id
    int lane = threadIdx.x & 31;
    if (gw >= n) return;
    const int base = gw * DDIM + lane * 4;

    const float4 q4 = *(const float4*)(Q + base);
    float4 acc = make_float4(0.f, 0.f, 0.f, 0.f);
    float den = 0.f;

    int s = off[gw], e = off[gw + 1];
    int c = (s < e) ? colArr[s] : 0;
    for (int i = s; i < e; i++) {
        int cn = (i + 1 < e) ? colArr[i + 1] : 0;
        const float4 k4 = *(const float4*)(Km + c * DDIM + lane * 4);
        const float4 v4 = *(const float4*)(V + c * DDIM + lane * 4);
        float d = q4.x * k4.x;
        d = fmaf(q4.y, k4.y, d);
        d = fmaf(q4.z, k4.z, d);
        d = fmaf(q4.w, k4.w, d);
        // reduce within 4-lane head group (head = 16 dims = 4 lanes)
        d += __shfl_xor_sync(0xffffffffu, d, 1);
        d += __shfl_xor_sync(0xffffffffu, d, 2);
        d = fminf(10.f, fmaxf(-10.f, d));
        float w = __expf(d);
        den += w;
        acc.x = fmaf(w, v4.x, acc.x);
        acc.y = fmaf(w, v4.y, acc.y);
        acc.z = fmaf(w, v4.z, acc.z);
        acc.w = fmaf(w, v4.w, acc.w);
        c = cn;
    }

    float inv = 1.f / (den + 1e-8f);
    float4 r = *(const float4*)(emb + base);
    r.x = fmaf(acc.x, inv, r.x);
    r.y = fmaf(acc.y, inv, r.y);
    r.z = fmaf(acc.z, inv, r.z);
    r.w = fmaf(acc.w, inv, r.w);

    float ss = r.x + r.y + r.z + r.w;
    #pragma unroll
    for (int o = 16; o; o >>= 1) ss += __shfl_xor_sync(0xffffffffu, ss, o);
    float mu = ss * (1.f / 128.f);

    float dx = r.x - mu, dy = r.y - mu, dz = r.z - mu, dw = r.w - mu;
    float vs = dx * dx + dy * dy + dz * dz + dw * dw;
    #pragma unroll
    for (int o = 16; o; o >>= 1) vs += __shfl_xor_sync(0xffffffffu, vs, o);
    float var = vs * (1.f / 128.f);
    float rstd = rsqrtf(var + 1e-6f);

    const float4 s4 = *(const float4*)(lns + lane * 4);
    const float4 b4 = *(const float4*)(lnb + lane * 4);
    float4 o4;
    o4.x = dx * rstd * s4.x + b4.x;
    o4.y = dy * rstd * s4.y + b4.y;
    o4.z = dz * rstd * s4.z + b4.z;
    o4.w = dw * rstd * s4.w + b4.w;
    *(float4*)(outp + base) = o4;
}

// ---------------- launch ----------------
extern "C" void kernel_launch(void* const* d_in, const int* in_sizes, int n_in,
                              void* d_out, int out_size)
{
    const float* x    = (const float*)d_in[0];
    const void*  ei   = d_in[1];
    const float* Wp   = (const float*)d_in[2];
    const float* Wpb  = (const float*)d_in[3];
    const float* Wpos = (const float*)d_in[4];
    const float* q1   = (const float*)d_in[5];
    const float* k1   = (const float*)d_in[6];
    const float* v1   = (const float*)d_in[7];
    const float* l1s  = (const float*)d_in[8];
    const float* l1b  = (const float*)d_in[9];
    const float* q2   = (const float*)d_in[10];
    const float* k2   = (const float*)d_in[11];
    const float* v2   = (const float*)d_in[12];
    const float* l2s  = (const float*)d_in[13];
    const float* l2b  = (const float*)d_in[14];
    const float* invw = (const float*)d_in[15];
    const float* invb = (const float*)d_in[16];

    const int D   = in_sizes[3];            // 128
    const int GIN = in_sizes[2] / D;        // 256
    int n = in_sizes[0] / GIN;              // 50000
    int E = in_sizes[1] / 2;                // 800000
    if (n > NMAX) n = NMAX;
    if (E > EMAX) E = EMAX;
    (void)D; (void)n_in; (void)out_size;

    float *emb, *emb2, *Qb, *Kb, *Vb;
    int *deg, *cur, *off, *col, *hiOr;
    cudaGetSymbolAddress((void**)&emb,  g_emb);
    cudaGetSymbolAddress((void**)&emb2, g_emb2);
    cudaGetSymbolAddress((void**)&Qb,   g_Q);
    cudaGetSymbolAddress((void**)&Kb,   g_K);
    cudaGetSymbolAddress((void**)&Vb,   g_V);
    cudaGetSymbolAddress((void**)&deg,  g_deg);
    cudaGetSymbolAddress((void**)&cur,  g_cur);
    cudaGetSymbolAddress((void**)&off,  g_off);
    cudaGetSymbolAddress((void**)&col,  g_col);
    cudaGetSymbolAddress((void**)&hiOr, g_hiOr);

    const int eb = (E + 255) / 256;
    const int gb = (n + 63) / 64;
    const int ab = (n + 7) / 8;

    // CSR build (dtype-agnostic)
    zero_kernel<<<(n + 255) / 256, 256>>>(deg, cur, hiOr, n);
    detect_kernel<<<16, 256>>>((const unsigned int*)ei, E, hiOr);
    hist_kernel<<<eb, 256>>>(ei, E, n, deg, hiOr);
    scan_kernel<<<1, 1024>>>(deg, off, n);
    scatter_kernel<<<eb, 256>>>(ei, E, n, off, cur, col, hiOr);

    // input projection + positional embedding
    gemm_kernel<256, 128><<<gb, 256>>>(x, Wp, Wpb, Wpos, emb, n);

    // layer 1
    gemm_kernel<128, 128><<<gb, 256>>>(emb, q1, nullptr, nullptr, Qb, n);
    gemm_kernel<128, 128><<<gb, 256>>>(emb, k1, nullptr, nullptr, Kb, n);
    gemm_kernel<128, 128><<<gb, 256>>>(emb, v1, nullptr, nullptr, Vb, n);
    agg_ln_kernel<<<ab, 256>>>(Qb, Kb, Vb, emb, off, col, l1s, l1b, emb2, n);

    // layer 2
    gemm_kernel<128, 128><<<gb, 256>>>(emb2, q2, nullptr, nullptr, Qb, n);
    gemm_kernel<128, 128><<<gb, 256>>>(emb2, k2, nullptr, nullptr, Kb, n);
    gemm_kernel<128, 128><<<gb, 256>>>(emb2, v2, nullptr, nullptr, Vb, n);
    agg_ln_kernel<<<ab, 256>>>(Qb, Kb, Vb, emb2, off, col, l2s, l2b, emb, n);

    // output projection
    gemm_kernel<128, 256><<<gb, 256>>>(emb, invw, invb, nullptr, (float*)d_out, n);
}

// round 3
// speedup vs baseline: 1.5955x; 1.5955x over previous
#include <cuda_runtime.h>
#include <cuda_bf16.h>
#include <mma.h>
#include <math.h>
#include <stdint.h>

using namespace nvcuda;

#define NMAX 50000
#define EMAX 800000
#define DDIM 128

// ---------------- device scratch (no allocations allowed) ----------------
__device__ float g_emb [NMAX * DDIM];
__device__ float g_emb2[NMAX * DDIM];
__device__ float g_Q   [NMAX * DDIM];
__device__ float g_K   [NMAX * DDIM];
__device__ float g_V   [NMAX * DDIM];
__device__ int   g_deg [NMAX];
__device__ int   g_cur [NMAX];
__device__ int   g_off [NMAX + 1];
__device__ int   g_col [EMAX];
__device__ int   g_hiOr;
// transposed bf16 weights (hi/lo): Wt[m][k] = W[k][m]
// Wp[0,32768) q1[32768) k1[49152) v1[65536) q2[81920) k2[98304) v2[114688) invw[131072,163840)
__device__ __nv_bfloat16 g_wh[163840];
__device__ __nv_bfloat16 g_wl[163840];

// ---------------- CSR build kernels ----------------
__global__ void detect_kernel(const unsigned int* __restrict__ p, int E, int* hiOr)
{
    int i = blockIdx.x * blockDim.x + threadIdx.x;
    int S = (E < 4096) ? E : 4096;
    if (i < S) {
        if (p[2 * i + 1] != 0u) atomicOr(hiOr, 1);
    }
}

__device__ __forceinline__ int eidx_at(const void* p, int i, bool i64)
{
    if (i64) return (int)(((const long long*)p)[i]);
    return ((const int*)p)[i];
}

__global__ void hist_kernel(const void* __restrict__ ei, int E, int n,
                            int* __restrict__ deg, const int* __restrict__ hiOr)
{
    bool i64 = (*hiOr == 0);
    int e = blockIdx.x * blockDim.x + threadIdx.x;
    if (e < E) {
        int r = eidx_at(ei, e, i64);
        if ((unsigned)r < (unsigned)n) atomicAdd(&deg[r], 1);
    }
}

__global__ void scan_kernel(const int* __restrict__ deg, int* __restrict__ off, int n)
{
    __shared__ int warpTot[32];
    const int tid = threadIdx.x;
    const int lane = tid & 31, wid = tid >> 5;
    int carry = 0;
    for (int base = 0; base < n; base += 4096) {
        int i0 = base + tid * 4;
        int v0 = (i0     < n) ? deg[i0]     : 0;
        int v1 = (i0 + 1 < n) ? deg[i0 + 1] : 0;
        int v2 = (i0 + 2 < n) ? deg[i0 + 2] : 0;
        int v3 = (i0 + 3 < n) ? deg[i0 + 3] : 0;
        int s = v0 + v1 + v2 + v3;
        int x = s;
        #pragma unroll
        for (int o = 1; o < 32; o <<= 1) {
            int t = __shfl_up_sync(0xffffffffu, x, o);
            if (lane >= o) x += t;
        }
        if (lane == 31) warpTot[wid] = x;
        __syncthreads();
        if (wid == 0) {
            int y = warpTot[lane];
            #pragma unroll
            for (int o = 1; o < 32; o <<= 1) {
                int t = __shfl_up_sync(0xffffffffu, y, o);
                if (lane >= o) y += t;
            }
            warpTot[lane] = y;
        }
        __syncthreads();
        int wp = (wid == 0) ? 0 : warpTot[wid - 1];
        int excl = carry + wp + x - s;
        if (i0     < n) off[i0]     = excl;
        if (i0 + 1 < n) off[i0 + 1] = excl + v0;
        if (i0 + 2 < n) off[i0 + 2] = excl + v0 + v1;
        if (i0 + 3 < n) off[i0 + 3] = excl + v0 + v1 + v2;
        carry += warpTot[31];
        __syncthreads();
    }
    if (tid == 0) off[n] = carry;
}

__global__ void scatter_kernel(const void* __restrict__ ei, int E, int n,
                               const int* __restrict__ off, int* __restrict__ cur,
                               int* __restrict__ col, const int* __restrict__ hiOr)
{
    bool i64 = (*hiOr == 0);
    int e = blockIdx.x * blockDim.x + threadIdx.x;
    if (e < E) {
        int r = eidx_at(ei, e, i64);
        int c = eidx_at(ei, E + e, i64);
        if ((unsigned)r < (unsigned)n) {
            int pos = off[r] + atomicAdd(&cur[r], 1);
            if ((unsigned)c >= (unsigned)n) c = 0;
            col[pos] = c;
        }
    }
}

// ---------------- weight prep: fp32 W[K,M] -> bf16 hi/lo Wt[M,K] ----------
__global__ void prep_weights(const float* __restrict__ Wp,
                             const float* __restrict__ q1, const float* __restrict__ k1,
                             const float* __restrict__ v1,
                             const float* __restrict__ q2, const float* __restrict__ k2,
                             const float* __restrict__ v2,
                             const float* __restrict__ invw,
                             __nv_bfloat16* __restrict__ wh, __nv_bfloat16* __restrict__ wl)
{
    int idx = blockIdx.x * blockDim.x + threadIdx.x;
    if (idx >= 163840) return;
    const float* src;
    int base, M, K;
    if (idx < 32768)       { src = Wp;   base = 0;      M = 128; K = 256; }
    else if (idx < 131072) {
        int m = (idx - 32768) / 16384;
        const float* arr[6] = {q1, k1, v1, q2, k2, v2};
        src = arr[m]; base = 32768 + m * 16384; M = 128; K = 128;
    }
    else                   { src = invw; base = 131072; M = 256; K = 128; }
    int e = idx - base;
    int m = e / K, k = e - m * K;          // dst index (m, k)
    float v = src[(size_t)k * M + m];
    __nv_bfloat16 hi = __float2bfloat16(v);
    float lo = v - __bfloat162float(hi);
    wh[idx] = hi;
    wl[idx] = __float2bfloat16(lo);
}

// ---------------- WMMA bf16 hi/lo GEMM -----------------------------------
// C[n, mout] tile (128 x 128 per block) = A[n, K] @ W, W given transposed
// as Wt[m][k] in bf16 hi/lo. acc = Ah*Wh + Ah*Wl + Al*Wh (fp32).
template <int K, bool BIAS>
__global__ void __launch_bounds__(256)
gemm_wmma(const float* __restrict__ A,
          const __nv_bfloat16* __restrict__ Wth, const __nv_bfloat16* __restrict__ Wtl,
          const float* __restrict__ b1, const float* __restrict__ b2,
          float* __restrict__ C, int n, int mout)
{
    constexpr int KC  = 64;
    constexpr int LDA = KC + 8;   // 72 elems
    constexpr int NKC = K / KC;
    extern __shared__ __align__(16) char smem[];
    __nv_bfloat16* sAh = (__nv_bfloat16*)smem;                    // 128*72
    __nv_bfloat16* sAl = sAh + 128 * LDA;
    __nv_bfloat16* sWh = sAl + 128 * LDA;
    __nv_bfloat16* sWl = sWh + 128 * LDA;

    const int tid = threadIdx.x;
    const int warp = tid >> 5;
    const int wr = warp >> 1;          // 0..3  (32-row strip)
    const int wc = warp & 1;           // 0..1  (64-col strip)
    const int rowBase = blockIdx.x * 128;
    const int colBase = blockIdx.y * 128;

    wmma::fragment<wmma::accumulator, 16, 16, 16, float> acc[2][4];
    #pragma unroll
    for (int i = 0; i < 2; i++)
        #pragma unroll
        for (int j = 0; j < 4; j++) wmma::fill_fragment(acc[i][j], 0.0f);

    for (int kc = 0; kc < NKC; kc++) {
        const int k0 = kc * KC;
        // stage A chunk: 128 rows x 64 cols fp32 -> bf16 hi/lo
        #pragma unroll
        for (int it = 0; it < 8; it++) {
            int idx = tid + it * 256;            // 2048 quads
            int r = idx >> 4, c4 = (idx & 15) * 4;
            float4 v = make_float4(0.f, 0.f, 0.f, 0.f);
            int row = rowBase + r;
            if (row < n) v = *(const float4*)(A + (size_t)row * K + k0 + c4);
            __nv_bfloat16 hx = __float2bfloat16(v.x);
            __nv_bfloat16 hy = __float2bfloat16(v.y);
            __nv_bfloat16 hz = __float2bfloat16(v.z);
            __nv_bfloat16 hw = __float2bfloat16(v.w);
            __nv_bfloat16 lx = __float2bfloat16(v.x - __bfloat162float(hx));
            __nv_bfloat16 ly = __float2bfloat16(v.y - __bfloat162float(hy));
            __nv_bfloat16 lz = __float2bfloat16(v.z - __bfloat162float(hz));
            __nv_bfloat16 lw = __float2bfloat16(v.w - __bfloat162float(hw));
            uint2 hv, lv;
            hv.x = ((uint32_t)__bfloat16_as_ushort(hy) << 16) | __bfloat16_as_ushort(hx);
            hv.y = ((uint32_t)__bfloat16_as_ushort(hw) << 16) | __bfloat16_as_ushort(hz);
            lv.x = ((uint32_t)__bfloat16_as_ushort(ly) << 16) | __bfloat16_as_ushort(lx);
            lv.y = ((uint32_t)__bfloat16_as_ushort(lw) << 16) | __bfloat16_as_ushort(lz);
            *(uint2*)(sAh + r * LDA + c4) = hv;
            *(uint2*)(sAl + r * LDA + c4) = lv;
        }
        // stage W chunk: 128 out-cols x 64 k (bf16, already transposed)
        #pragma unroll
        for (int it = 0; it < 4; it++) {
            int idx = tid + it * 256;            // 1024 groups of 8 bf16
            int r = idx >> 3, c8 = (idx & 7) * 8;
            const size_t g = (size_t)(colBase + r) * K + k0 + c8;
            *(uint4*)(sWh + r * LDA + c8) = *(const uint4*)(Wth + g);
            *(uint4*)(sWl + r * LDA + c8) = *(const uint4*)(Wtl + g);
        }
        __syncthreads();

        #pragma unroll
        for (int ks = 0; ks < KC / 16; ks++) {
            wmma::fragment<wmma::matrix_a, 16, 16, 16, __nv_bfloat16, wmma::row_major> ah[2], al[2];
            wmma::fragment<wmma::matrix_b, 16, 16, 16, __nv_bfloat16, wmma::col_major> bh[4], bl[4];
            #pragma unroll
            for (int i = 0; i < 2; i++) {
                const __nv_bfloat16* p = sAh + (wr * 32 + i * 16) * LDA + ks * 16;
                wmma::load_matrix_sync(ah[i], p, LDA);
                wmma::load_matrix_sync(al[i], p + 128 * LDA, LDA);   // sAl follows sAh
            }
            #pragma unroll
            for (int j = 0; j < 4; j++) {
                const __nv_bfloat16* p = sWh + (wc * 64 + j * 16) * LDA + ks * 16;
                wmma::load_matrix_sync(bh[j], p, LDA);
                wmma::load_matrix_sync(bl[j], p + 128 * LDA, LDA);   // sWl follows sWh
            }
            #pragma unroll
            for (int i = 0; i < 2; i++)
                #pragma unroll
                for (int j = 0; j < 4; j++) {
                    wmma::mma_sync(acc[i][j], ah[i], bh[j], acc[i][j]);
                    wmma::mma_sync(acc[i][j], ah[i], bl[j], acc[i][j]);
                    wmma::mma_sync(acc[i][j], al[i], bh[j], acc[i][j]);
                }
        }
        __syncthreads();
    }

    // epilogue via smem (guarded rows, fused bias)
    float* sC = (float*)smem;                    // 128 x 132
    #pragma unroll
    for (int i = 0; i < 2; i++)
        #pragma unroll
        for (int j = 0; j < 4; j++)
            wmma::store_matrix_sync(sC + (wr * 32 + i * 16) * 132 + wc * 64 + j * 16,
                                    acc[i][j], 132, wmma::mem_row_major);
    __syncthreads();
    #pragma unroll
    for (int it = 0; it < 16; it++) {
        int idx = tid + it * 256;                // 4096 quads
        int r = idx >> 5, c4 = (idx & 31) * 4;
        int row = rowBase + r;
        if (row < n) {
            float4 v = *(float4*)(sC + r * 132 + c4);
            if (BIAS) {
                int col = colBase + c4;
                v.x += b1[col];     v.y += b1[col + 1];
                v.z += b1[col + 2]; v.w += b1[col + 3];
                if (b2) {
                    v.x += b2[col];     v.y += b2[col + 1];
                    v.z += b2[col + 2]; v.w += b2[col + 3];
                }
            }
            *(float4*)(C + (size_t)row * mout + colBase + c4) = v;
        }
    }
}

// ---------------- warp-per-node: attention agg + residual + LayerNorm ----
__launch_bounds__(256)
__global__ void agg_ln_kernel(const float* __restrict__ Q, const float* __restrict__ Km,
                              const float* __restrict__ V, const float* __restrict__ emb,
                              const int* __restrict__ off, const int* __restrict__ colArr,
                              const float* __restrict__ lns, const float* __restrict__ lnb,
                              float* __restrict__ outp, int n)
{
    int gw = (blockIdx.x * blockDim.x + threadIdx.x) >> 5;   // node id
    int lane = threadIdx.x & 31;
    if (gw >= n) return;
    const int base = gw * DDIM + lane * 4;

    const float4 q4 = *(const float4*)(Q + base);
    float4 acc = make_float4(0.f, 0.f, 0.f, 0.f);
    float den = 0.f;

    int s = off[gw], e = off[gw + 1];
    int c = (s < e) ? colArr[s] : 0;
    for (int i = s; i < e; i++) {
        int cn = (i + 1 < e) ? colArr[i + 1] : 0;
        const float4 k4 = *(const float4*)(Km + c * DDIM + lane * 4);
        const float4 v4 = *(const float4*)(V + c * DDIM + lane * 4);
        float d = q4.x * k4.x;
        d = fmaf(q4.y, k4.y, d);
        d = fmaf(q4.z, k4.z, d);
        d = fmaf(q4.w, k4.w, d);
        d += __shfl_xor_sync(0xffffffffu, d, 1);
        d += __shfl_xor_sync(0xffffffffu, d, 2);
        d = fminf(10.f, fmaxf(-10.f, d));
        float w = __expf(d);
        den += w;
        acc.x = fmaf(w, v4.x, acc.x);
        acc.y = fmaf(w, v4.y, acc.y);
        acc.z = fmaf(w, v4.z, acc.z);
        acc.w = fmaf(w, v4.w, acc.w);
        c = cn;
    }

    float inv = 1.f / (den + 1e-8f);
    float4 r = *(const float4*)(emb + base);
    r.x = fmaf(acc.x, inv, r.x);
    r.y = fmaf(acc.y, inv, r.y);
    r.z = fmaf(acc.z, inv, r.z);
    r.w = fmaf(acc.w, inv, r.w);

    float ss = r.x + r.y + r.z + r.w;
    #pragma unroll
    for (int o = 16; o; o >>= 1) ss += __shfl_xor_sync(0xffffffffu, ss, o);
    float mu = ss * (1.f / 128.f);

    float dx = r.x - mu, dy = r.y - mu, dz = r.z - mu, dw = r.w - mu;
    float vs = dx * dx + dy * dy + dz * dz + dw * dw;
    #pragma unroll
    for (int o = 16; o; o >>= 1) vs += __shfl_xor_sync(0xffffffffu, vs, o);
    float var = vs * (1.f / 128.f);
    float rstd = rsqrtf(var + 1e-6f);

    const float4 s4 = *(const float4*)(lns + lane * 4);
    const float4 b4 = *(const float4*)(lnb + lane * 4);
    float4 o4;
    o4.x = dx * rstd * s4.x + b4.x;
    o4.y = dy * rstd * s4.y + b4.y;
    o4.z = dz * rstd * s4.z + b4.z;
    o4.w = dw * rstd * s4.w + b4.w;
    *(float4*)(outp + base) = o4;
}

// ---------------- launch ----------------
extern "C" void kernel_launch(void* const* d_in, const int* in_sizes, int n_in,
                              void* d_out, int out_size)
{
    const float* x    = (const float*)d_in[0];
    const void*  ei   = d_in[1];
    const float* Wp   = (const float*)d_in[2];
    const float* Wpb  = (const float*)d_in[3];
    const float* Wpos = (const float*)d_in[4];
    const float* q1   = (const float*)d_in[5];
    const float* k1   = (const float*)d_in[6];
    const float* v1   = (const float*)d_in[7];
    const float* l1s  = (const float*)d_in[8];
    const float* l1b  = (const float*)d_in[9];
    const float* q2   = (const float*)d_in[10];
    const float* k2   = (const float*)d_in[11];
    const float* v2   = (const float*)d_in[12];
    const float* l2s  = (const float*)d_in[13];
    const float* l2b  = (const float*)d_in[14];
    const float* invw = (const float*)d_in[15];
    const float* invb = (const float*)d_in[16];

    const int D   = in_sizes[3];            // 128
    const int GIN = in_sizes[2] / D;        // 256
    int n = in_sizes[0] / GIN;              // 50000
    int E = in_sizes[1] / 2;                // 800000
    if (n > NMAX) n = NMAX;
    if (E > EMAX) E = EMAX;
    (void)D; (void)n_in; (void)out_size;

    float *emb, *emb2, *Qb, *Kb, *Vb;
    int *deg, *cur, *off, *col, *hiOr;
    __nv_bfloat16 *wh, *wl;
    cudaGetSymbolAddress((void**)&emb,  g_emb);
    cudaGetSymbolAddress((void**)&emb2, g_emb2);
    cudaGetSymbolAddress((void**)&Qb,   g_Q);
    cudaGetSymbolAddress((void**)&Kb,   g_K);
    cudaGetSymbolAddress((void**)&Vb,   g_V);
    cudaGetSymbolAddress((void**)&deg,  g_deg);
    cudaGetSymbolAddress((void**)&cur,  g_cur);
    cudaGetSymbolAddress((void**)&off,  g_off);
    cudaGetSymbolAddress((void**)&col,  g_col);
    cudaGetSymbolAddress((void**)&hiOr, g_hiOr);
    cudaGetSymbolAddress((void**)&wh,   g_wh);
    cudaGetSymbolAddress((void**)&wl,   g_wl);

    const int SMEM = 4 * 128 * 72 * 2;      // 73728 bytes
    cudaFuncSetAttribute(gemm_wmma<256, true>,
                         cudaFuncAttributeMaxDynamicSharedMemorySize, SMEM);
    cudaFuncSetAttribute(gemm_wmma<128, false>,
                         cudaFuncAttributeMaxDynamicSharedMemorySize, SMEM);
    cudaFuncSetAttribute(gemm_wmma<128, true>,
                         cudaFuncAttributeMaxDynamicSharedMemorySize, SMEM);

    const int eb  = (E + 255) / 256;
    const int gb  = (n + 127) / 128;
    const int ab  = (n + 7) / 8;

    // CSR build
    cudaMemsetAsync(deg, 0, (size_t)n * sizeof(int));
    cudaMemsetAsync(cur, 0, (size_t)n * sizeof(int));
    cudaMemsetAsync(hiOr, 0, sizeof(int));
    detect_kernel<<<16, 256>>>((const unsigned int*)ei, E, hiOr);
    hist_kernel<<<eb, 256>>>(ei, E, n, deg, hiOr);
    scan_kernel<<<1, 1024>>>(deg, off, n);
    scatter_kernel<<<eb, 256>>>(ei, E, n, off, cur, col, hiOr);

    // weight prep (bf16 hi/lo, transposed)
    prep_weights<<<640, 256>>>(Wp, q1, k1, v1, q2, k2, v2, invw, wh, wl);

    // input projection + bias + positional embedding
    gemm_wmma<256, true><<<dim3(gb, 1), 256, SMEM>>>(
        x, wh, wl, Wpb, Wpos, emb, n, 128);

    // layer 1
    gemm_wmma<128, false><<<dim3(gb, 1), 256, SMEM>>>(
        emb, wh + 32768, wl + 32768, nullptr, nullptr, Qb, n, 128);
    gemm_wmma<128, false><<<dim3(gb, 1), 256, SMEM>>>(
        emb, wh + 49152, wl + 49152, nullptr, nullptr, Kb, n, 128);
    gemm_wmma<128, false><<<dim3(gb, 1), 256, SMEM>>>(
        emb, wh + 65536, wl + 65536, nullptr, nullptr, Vb, n, 128);
    agg_ln_kernel<<<ab, 256>>>(Qb, Kb, Vb, emb, off, col, l1s, l1b, emb2, n);

    // layer 2
    gemm_wmma<128, false><<<dim3(gb, 1), 256, SMEM>>>(
        emb2, wh + 81920, wl + 81920, nullptr, nullptr, Qb, n, 128);
    gemm_wmma<128, false><<<dim3(gb, 1), 256, SMEM>>>(
        emb2, wh + 98304, wl + 98304, nullptr, nullptr, Kb, n, 128);
    gemm_wmma<128, false><<<dim3(gb, 1), 256, SMEM>>>(
        emb2, wh + 114688, wl + 114688, nullptr, nullptr, Vb, n, 128);
    agg_ln_kernel<<<ab, 256>>>(Qb, Kb, Vb, emb2, off, col, l2s, l2b, emb, n);

    // output projection (256 cols -> grid.y = 2)
    gemm_wmma<128, true><<<dim3(gb, 2), 256, SMEM>>>(
        emb, wh + 131072, wl + 131072, invb, nullptr, (float*)d_out, n, 256);
}

// round 4
// speedup vs baseline: 1.6314x; 1.0225x over previous
#include <cuda_runtime.h>
#include <cuda_bf16.h>
#include <mma.h>
#include <math.h>
#include <stdint.h>

using namespace nvcuda;

#define NMAX 50000
#define EMAX 800000
#define DDIM 128

// ---------------- device scratch (no allocations allowed) ----------------
__device__ float g_emb [NMAX * DDIM];
__device__ float g_emb2[NMAX * DDIM];
__device__ float g_Q   [NMAX * DDIM];
__device__ float g_K   [NMAX * DDIM];
__device__ float g_V   [NMAX * DDIM];
__device__ int   g_deg [NMAX];
__device__ int   g_cur [NMAX];
__device__ int   g_off [NMAX + 1];
__device__ int   g_col [EMAX];
__device__ int   g_hiOr;
// transposed bf16 weights (hi/lo): Wt[m][k] = W[k][m]
__device__ __nv_bfloat16 g_wh[163840];
__device__ __nv_bfloat16 g_wl[163840];
// pre-converted activations (hi/lo)
__device__ __nv_bfloat16 g_xh[NMAX * 256];
__device__ __nv_bfloat16 g_xl[NMAX * 256];
__device__ __nv_bfloat16 g_eh[NMAX * DDIM];
__device__ __nv_bfloat16 g_el[NMAX * DDIM];

// ---------------- CSR build kernels ----------------
__global__ void detect_kernel(const unsigned int* __restrict__ p, int E, int* hiOr)
{
    int i = blockIdx.x * blockDim.x + threadIdx.x;
    int S = (E < 4096) ? E : 4096;
    if (i < S) {
        if (p[2 * i + 1] != 0u) atomicOr(hiOr, 1);
    }
}

__device__ __forceinline__ int eidx_at(const void* p, int i, bool i64)
{
    if (i64) return (int)(((const long long*)p)[i]);
    return ((const int*)p)[i];
}

__global__ void hist_kernel(const void* __restrict__ ei, int E, int n,
                            int* __restrict__ deg, const int* __restrict__ hiOr)
{
    bool i64 = (*hiOr == 0);
    int e = blockIdx.x * blockDim.x + threadIdx.x;
    if (e < E) {
        int r = eidx_at(ei, e, i64);
        if ((unsigned)r < (unsigned)n) atomicAdd(&deg[r], 1);
    }
}

__global__ void scan_kernel(const int* __restrict__ deg, int* __restrict__ off, int n)
{
    __shared__ int warpTot[32];
    const int tid = threadIdx.x;
    const int lane = tid & 31, wid = tid >> 5;
    int carry = 0;
    for (int base = 0; base < n; base += 4096) {
        int i0 = base + tid * 4;
        int v0 = (i0     < n) ? deg[i0]     : 0;
        int v1 = (i0 + 1 < n) ? deg[i0 + 1] : 0;
        int v2 = (i0 + 2 < n) ? deg[i0 + 2] : 0;
        int v3 = (i0 + 3 < n) ? deg[i0 + 3] : 0;
        int s = v0 + v1 + v2 + v3;
        int x = s;
        #pragma unroll
        for (int o = 1; o < 32; o <<= 1) {
            int t = __shfl_up_sync(0xffffffffu, x, o);
            if (lane >= o) x += t;
        }
        if (lane == 31) warpTot[wid] = x;
        __syncthreads();
        if (wid == 0) {
            int y = warpTot[lane];
            #pragma unroll
            for (int o = 1; o < 32; o <<= 1) {
                int t = __shfl_up_sync(0xffffffffu, y, o);
                if (lane >= o) y += t;
            }
            warpTot[lane] = y;
        }
        __syncthreads();
        int wp = (wid == 0) ? 0 : warpTot[wid - 1];
        int excl = carry + wp + x - s;
        if (i0     < n) off[i0]     = excl;
        if (i0 + 1 < n) off[i0 + 1] = excl + v0;
        if (i0 + 2 < n) off[i0 + 2] = excl + v0 + v1;
        if (i0 + 3 < n) off[i0 + 3] = excl + v0 + v1 + v2;
        carry += warpTot[31];
        __syncthreads();
    }
    if (tid == 0) off[n] = carry;
}

__global__ void scatter_kernel(const void* __restrict__ ei, int E, int n,
                               const int* __restrict__ off, int* __restrict__ cur,
                               int* __restrict__ col, const int* __restrict__ hiOr)
{
    bool i64 = (*hiOr == 0);
    int e = blockIdx.x * blockDim.x + threadIdx.x;
    if (e < E) {
        int r = eidx_at(ei, e, i64);
        int c = eidx_at(ei, E + e, i64);
        if ((unsigned)r < (unsigned)n) {
            int pos = off[r] + atomicAdd(&cur[r], 1);
            if ((unsigned)c >= (unsigned)n) c = 0;
            col[pos] = c;
        }
    }
}

// ---------------- weight prep: fp32 W[K,M] -> bf16 hi/lo Wt[M,K] ----------
__global__ void prep_weights(const float* __restrict__ Wp,
                             const float* __restrict__ q1, const float* __restrict__ k1,
                             const float* __restrict__ v1,
                             const float* __restrict__ q2, const float* __restrict__ k2,
                             const float* __restrict__ v2,
                             const float* __restrict__ invw,
                             __nv_bfloat16* __restrict__ wh, __nv_bfloat16* __restrict__ wl)
{
    int idx = blockIdx.x * blockDim.x + threadIdx.x;
    if (idx >= 163840) return;
    const float* src;
    int base, M, K;
    if (idx < 32768)       { src = Wp;   base = 0;      M = 128; K = 256; }
    else if (idx < 131072) {
        int m = (idx - 32768) / 16384;
        const float* arr[6] = {q1, k1, v1, q2, k2, v2};
        src = arr[m]; base = 32768 + m * 16384; M = 128; K = 128;
    }
    else                   { src = invw; base = 131072; M = 256; K = 128; }
    int e = idx - base;
    int m = e / K, k = e - m * K;          // dst index (m, k)
    float v = src[(size_t)k * M + m];
    __nv_bfloat16 hi = __float2bfloat16(v);
    float lo = v - __bfloat162float(hi);
    wh[idx] = hi;
    wl[idx] = __float2bfloat16(lo);
}

// ---------------- activation pre-convert: fp32 -> bf16 hi/lo --------------
__device__ __forceinline__ void split4(float4 v, uint2& hv, uint2& lv)
{
    __nv_bfloat16 hx = __float2bfloat16(v.x);
    __nv_bfloat16 hy = __float2bfloat16(v.y);
    __nv_bfloat16 hz = __float2bfloat16(v.z);
    __nv_bfloat16 hw = __float2bfloat16(v.w);
    __nv_bfloat16 lx = __float2bfloat16(v.x - __bfloat162float(hx));
    __nv_bfloat16 ly = __float2bfloat16(v.y - __bfloat162float(hy));
    __nv_bfloat16 lz = __float2bfloat16(v.z - __bfloat162float(hz));
    __nv_bfloat16 lw = __float2bfloat16(v.w - __bfloat162float(hw));
    hv.x = ((uint32_t)__bfloat16_as_ushort(hy) << 16) | __bfloat16_as_ushort(hx);
    hv.y = ((uint32_t)__bfloat16_as_ushort(hw) << 16) | __bfloat16_as_ushort(hz);
    lv.x = ((uint32_t)__bfloat16_as_ushort(ly) << 16) | __bfloat16_as_ushort(lx);
    lv.y = ((uint32_t)__bfloat16_as_ushort(lw) << 16) | __bfloat16_as_ushort(lz);
}

__global__ void conv_x_kernel(const float* __restrict__ A,
                              __nv_bfloat16* __restrict__ oh, __nv_bfloat16* __restrict__ ol,
                              int total4)
{
    int i = blockIdx.x * blockDim.x + threadIdx.x;
    if (i >= total4) return;
    float4 v = *(const float4*)(A + (size_t)i * 4);
    uint2 hv, lv;
    split4(v, hv, lv);
    *(uint2*)(oh + (size_t)i * 4) = hv;
    *(uint2*)(ol + (size_t)i * 4) = lv;
}

// ---------------- WMMA bf16 hi/lo GEMM (pre-converted A) ------------------
// For o in [0,NOUT): C_o[128-row tile, 128-col tile] = A @ W_o
// A given as bf16 hi/lo [n, K]; W transposed bf16 hi/lo Wt[m][k].
// acc = Ah*Wh + Ah*Wl + Al*Wh (fp32 accum).
template <int K, int NOUT, bool BIAS>
__global__ void __launch_bounds__(256)
gemm_pre(const __nv_bfloat16* __restrict__ Ah, const __nv_bfloat16* __restrict__ Al,
         const __nv_bfloat16* __restrict__ Wth, const __nv_bfloat16* __restrict__ Wtl,
         const float* __restrict__ b1, const float* __restrict__ b2,
         float* __restrict__ C0, float* __restrict__ C1, float* __restrict__ C2,
         __nv_bfloat16* __restrict__ oh, __nv_bfloat16* __restrict__ ol,
         int n, int mout)
{
    constexpr int KC  = 64;
    constexpr int LDA = KC + 8;   // 72 elems
    constexpr int NKC = K / KC;
    constexpr int WSTRIDE = K * 128;   // elems per weight matrix (M=128 outputs)
    extern __shared__ __align__(16) char smem[];
    __nv_bfloat16* sAh = (__nv_bfloat16*)smem;                    // 128*72
    __nv_bfloat16* sAl = sAh + 128 * LDA;
    __nv_bfloat16* sWh = sAl + 128 * LDA;
    __nv_bfloat16* sWl = sWh + 128 * LDA;

    const int tid = threadIdx.x;
    const int warp = tid >> 5;
    const int wr = warp >> 1;          // 0..3  (32-row strip)
    const int wc = warp & 1;           // 0..1  (64-col strip)
    const int rowBase = blockIdx.x * 128;
    const int colBase = blockIdx.y * 128;

    #pragma unroll
    for (int o = 0; o < NOUT; o++) {
        wmma::fragment<wmma::accumulator, 16, 16, 16, float> acc[2][4];
        #pragma unroll
        for (int i = 0; i < 2; i++)
            #pragma unroll
            for (int j = 0; j < 4; j++) wmma::fill_fragment(acc[i][j], 0.0f);

        const __nv_bfloat16* Wh_o = Wth + (size_t)o * WSTRIDE;
        const __nv_bfloat16* Wl_o = Wtl + (size_t)o * WSTRIDE;

        for (int kc = 0; kc < NKC; kc++) {
            const int k0 = kc * KC;
            // stage A chunk (pure copy, zero-fill OOB rows)
            #pragma unroll
            for (int it = 0; it < 4; it++) {
                int idx = tid + it * 256;            // 1024 uint4 each
                int r = idx >> 3, c8 = (idx & 7) * 8;
                int row = rowBase + r;
                uint4 hv = make_uint4(0u, 0u, 0u, 0u), lv = hv;
                if (row < n) {
                    size_t g = (size_t)row * K + k0 + c8;
                    hv = *(const uint4*)(Ah + g);
                    lv = *(const uint4*)(Al + g);
                }
                *(uint4*)(sAh + r * LDA + c8) = hv;
                *(uint4*)(sAl + r * LDA + c8) = lv;
            }
            // stage W chunk
            #pragma unroll
            for (int it = 0; it < 4; it++) {
                int idx = tid + it * 256;
                int r = idx >> 3, c8 = (idx & 7) * 8;
                size_t g = (size_t)(colBase + r) * K + k0 + c8;
                *(uint4*)(sWh + r * LDA + c8) = *(const uint4*)(Wh_o + g);
                *(uint4*)(sWl + r * LDA + c8) = *(const uint4*)(Wl_o + g);
            }
            __syncthreads();

            #pragma unroll
            for (int ks = 0; ks < KC / 16; ks++) {
                wmma::fragment<wmma::matrix_a, 16, 16, 16, __nv_bfloat16, wmma::row_major> ah[2], al[2];
                wmma::fragment<wmma::matrix_b, 16, 16, 16, __nv_bfloat16, wmma::col_major> bh[4], bl[4];
                #pragma unroll
                for (int i = 0; i < 2; i++) {
                    const __nv_bfloat16* p = sAh + (wr * 32 + i * 16) * LDA + ks * 16;
                    wmma::load_matrix_sync(ah[i], p, LDA);
                    wmma::load_matrix_sync(al[i], p + 128 * LDA, LDA);
                }
                #pragma unroll
                for (int j = 0; j < 4; j++) {
                    const __nv_bfloat16* p = sWh + (wc * 64 + j * 16) * LDA + ks * 16;
                    wmma::load_matrix_sync(bh[j], p, LDA);
                    wmma::load_matrix_sync(bl[j], p + 128 * LDA, LDA);
                }
                #pragma unroll
                for (int i = 0; i < 2; i++)
                    #pragma unroll
                    for (int j = 0; j < 4; j++) {
                        wmma::mma_sync(acc[i][j], ah[i], bh[j], acc[i][j]);
                        wmma::mma_sync(acc[i][j], ah[i], bl[j], acc[i][j]);
                        wmma::mma_sync(acc[i][j], al[i], bh[j], acc[i][j]);
                    }
            }
            __syncthreads();
        }

        // epilogue via smem (guarded rows, fused bias, optional hi/lo emit)
        float* sC = (float*)smem;                    // 128 x 132
        #pragma unroll
        for (int i = 0; i < 2; i++)
            #pragma unroll
            for (int j = 0; j < 4; j++)
                wmma::store_matrix_sync(sC + (wr * 32 + i * 16) * 132 + wc * 64 + j * 16,
                                        acc[i][j], 132, wmma::mem_row_major);
        __syncthreads();
        float* Cp = (o == 0) ? C0 : ((o == 1) ? C1 : C2);
        #pragma unroll
        for (int it = 0; it < 16; it++) {
            int idx = tid + it * 256;                // 4096 quads
            int r = idx >> 5, c4 = (idx & 31) * 4;
            int row = rowBase + r;
            if (row < n) {
                float4 v = *(float4*)(sC + r * 132 + c4);
                if (BIAS) {
                    int col = colBase + c4;
                    v.x += b1[col];     v.y += b1[col + 1];
                    v.z += b1[col + 2]; v.w += b1[col + 3];
                    if (b2) {
                        v.x += b2[col];     v.y += b2[col + 1];
                        v.z += b2[col + 2]; v.w += b2[col + 3];
                    }
                }
                size_t g = (size_t)row * mout + colBase + c4;
                *(float4*)(Cp + g) = v;
                if (oh) {
                    uint2 hv, lv;
                    split4(v, hv, lv);
                    *(uint2*)(oh + g) = hv;
                    *(uint2*)(ol + g) = lv;
                }
            }
        }
        __syncthreads();
    }
}

// ---------------- warp-per-node: attention agg + residual + LayerNorm ----
__launch_bounds__(256)
__global__ void agg_ln_kernel(const float* __restrict__ Q, const float* __restrict__ Km,
                              const float* __restrict__ V, const float* __restrict__ emb,
                              const int* __restrict__ off, const int* __restrict__ colArr,
                              const float* __restrict__ lns, const float* __restrict__ lnb,
                              float* __restrict__ outp,
                              __nv_bfloat16* __restrict__ oh, __nv_bfloat16* __restrict__ ol,
                              int n)
{
    int gw = (blockIdx.x * blockDim.x + threadIdx.x) >> 5;   // node id
    int lane = threadIdx.x & 31;
    if (gw >= n) return;
    const int base = gw * DDIM + lane * 4;

    const float4 q4 = *(const float4*)(Q + base);
    float4 acc = make_float4(0.f, 0.f, 0.f, 0.f);
    float den = 0.f;

    int s = off[gw], e = off[gw + 1];
    int c = (s < e) ? colArr[s] : 0;
    for (int i = s; i < e; i++) {
        int cn = (i + 1 < e) ? colArr[i + 1] : 0;
        const float4 k4 = *(const float4*)(Km + c * DDIM + lane * 4);
        const float4 v4 = *(const float4*)(V + c * DDIM + lane * 4);
        float d = q4.x * k4.x;
        d = fmaf(q4.y, k4.y, d);
        d = fmaf(q4.z, k4.z, d);
        d = fmaf(q4.w, k4.w, d);
        d += __shfl_xor_sync(0xffffffffu, d, 1);
        d += __shfl_xor_sync(0xffffffffu, d, 2);
        d = fminf(10.f, fmaxf(-10.f, d));
        float w = __expf(d);
        den += w;
        acc.x = fmaf(w, v4.x, acc.x);
        acc.y = fmaf(w, v4.y, acc.y);
        acc.z = fmaf(w, v4.z, acc.z);
        acc.w = fmaf(w, v4.w, acc.w);
        c = cn;
    }

    float inv = 1.f / (den + 1e-8f);
    float4 r = *(const float4*)(emb + base);
    r.x = fmaf(acc.x, inv, r.x);
    r.y = fmaf(acc.y, inv, r.y);
    r.z = fmaf(acc.z, inv, r.z);
    r.w = fmaf(acc.w, inv, r.w);

    float ss = r.x + r.y + r.z + r.w;
    #pragma unroll
    for (int o = 16; o; o >>= 1) ss += __shfl_xor_sync(0xffffffffu, ss, o);
    float mu = ss * (1.f / 128.f);

    float dx = r.x - mu, dy = r.y - mu, dz = r.z - mu, dw = r.w - mu;
    float vs = dx * dx + dy * dy + dz * dz + dw * dw;
    #pragma unroll
    for (int o = 16; o; o >>= 1) vs += __shfl_xor_sync(0xffffffffu, vs, o);
    float var = vs * (1.f / 128.f);
    float rstd = rsqrtf(var + 1e-6f);

    const float4 s4 = *(const float4*)(lns + lane * 4);
    const float4 b4 = *(const float4*)(lnb + lane * 4);
    float4 o4;
    o4.x = dx * rstd * s4.x + b4.x;
    o4.y = dy * rstd * s4.y + b4.y;
    o4.z = dz * rstd * s4.z + b4.z;
    o4.w = dw * rstd * s4.w + b4.w;
    *(float4*)(outp + base) = o4;
    uint2 hv, lv;
    split4(o4, hv, lv);
    *(uint2*)(oh + base) = hv;
    *(uint2*)(ol + base) = lv;
}

// ---------------- launch ----------------
extern "C" void kernel_launch(void* const* d_in, const int* in_sizes, int n_in,
                              void* d_out, int out_size)
{
    const float* x    = (const float*)d_in[0];
    const void*  ei   = d_in[1];
    const float* Wp   = (const float*)d_in[2];
    const float* Wpb  = (const float*)d_in[3];
    const float* Wpos = (const float*)d_in[4];
    const float* q1   = (const float*)d_in[5];
    const float* k1   = (const float*)d_in[6];
    const float* v1   = (const float*)d_in[7];
    const float* l1s  = (const float*)d_in[8];
    const float* l1b  = (const float*)d_in[9];
    const float* q2   = (const float*)d_in[10];
    const float* k2   = (const float*)d_in[11];
    const float* v2   = (const float*)d_in[12];
    const float* l2s  = (const float*)d_in[13];
    const float* l2b  = (const float*)d_in[14];
    const float* invw = (const float*)d_in[15];
    const float* invb = (const float*)d_in[16];

    const int D   = in_sizes[3];            // 128
    const int GIN = in_sizes[2] / D;        // 256
    int n = in_sizes[0] / GIN;              // 50000
    int E = in_sizes[1] / 2;                // 800000
    if (n > NMAX) n = NMAX;
    if (E > EMAX) E = EMAX;
    (void)D; (void)n_in; (void)out_size;

    float *emb, *emb2, *Qb, *Kb, *Vb;
    int *deg, *cur, *off, *col, *hiOr;
    __nv_bfloat16 *wh, *wl, *xh, *xl, *eh, *el;
    cudaGetSymbolAddress((void**)&emb,  g_emb);
    cudaGetSymbolAddress((void**)&emb2, g_emb2);
    cudaGetSymbolAddress((void**)&Qb,   g_Q);
    cudaGetSymbolAddress((void**)&Kb,   g_K);
    cudaGetSymbolAddress((void**)&Vb,   g_V);
    cudaGetSymbolAddress((void**)&deg,  g_deg);
    cudaGetSymbolAddress((void**)&cur,  g_cur);
    cudaGetSymbolAddress((void**)&off,  g_off);
    cudaGetSymbolAddress((void**)&col,  g_col);
    cudaGetSymbolAddress((void**)&hiOr, g_hiOr);
    cudaGetSymbolAddress((void**)&wh,   g_wh);
    cudaGetSymbolAddress((void**)&wl,   g_wl);
    cudaGetSymbolAddress((void**)&xh,   g_xh);
    cudaGetSymbolAddress((void**)&xl,   g_xl);
    cudaGetSymbolAddress((void**)&eh,   g_eh);
    cudaGetSymbolAddress((void**)&el,   g_el);

    const int SMEM = 4 * 128 * 72 * 2;      // 73728 bytes
    cudaFuncSetAttribute(gemm_pre<256, 1, true>,
                         cudaFuncAttributeMaxDynamicSharedMemorySize, SMEM);
    cudaFuncSetAttribute(gemm_pre<128, 3, false>,
                         cudaFuncAttributeMaxDynamicSharedMemorySize, SMEM);
    cudaFuncSetAttribute(gemm_pre<128, 1, true>,
                         cudaFuncAttributeMaxDynamicSharedMemorySize, SMEM);

    const int eb  = (E + 255) / 256;
    const int gb  = (n + 127) / 128;
    const int ab  = (n + 7) / 8;

    // CSR build
    cudaMemsetAsync(deg, 0, (size_t)n * sizeof(int));
    cudaMemsetAsync(cur, 0, (size_t)n * sizeof(int));
    cudaMemsetAsync(hiOr, 0, sizeof(int));
    detect_kernel<<<16, 256>>>((const unsigned int*)ei, E, hiOr);
    hist_kernel<<<eb, 256>>>(ei, E, n, deg, hiOr);
    scan_kernel<<<1, 1024>>>(deg, off, n);
    scatter_kernel<<<eb, 256>>>(ei, E, n, off, cur, col, hiOr);

    // weight prep + x pre-convert
    prep_weights<<<640, 256>>>(Wp, q1, k1, v1, q2, k2, v2, invw, wh, wl);
    const int xq = n * GIN / 4;
    conv_x_kernel<<<(xq + 255) / 256, 256>>>(x, xh, xl, xq);

    // input projection + bias + positional embedding (emits emb fp32 + hi/lo)
    gemm_pre<256, 1, true><<<dim3(gb, 1), 256, SMEM>>>(
        xh, xl, wh, wl, Wpb, Wpos, emb, nullptr, nullptr, eh, el, n, 128);

    // layer 1: fused QKV, then aggregate+LN (emits emb2 fp32 + hi/lo)
    gemm_pre<128, 3, false><<<dim3(gb, 1), 256, SMEM>>>(
        eh, el, wh + 32768, wl + 32768, nullptr, nullptr, Qb, Kb, Vb,
        nullptr, nullptr, n, 128);
    agg_ln_kernel<<<ab, 256>>>(Qb, Kb, Vb, emb, off, col, l1s, l1b, emb2, eh, el, n);

    // layer 2
    gemm_pre<128, 3, false><<<dim3(gb, 1), 256, SMEM>>>(
        eh, el, wh + 81920, wl + 81920, nullptr, nullptr, Qb, Kb, Vb,
        nullptr, nullptr, n, 128);
    agg_ln_kernel<<<ab, 256>>>(Qb, Kb, Vb, emb2, off, col, l2s, l2b, emb, eh, el, n);

    // output projection (256 cols -> grid.y = 2)
    gemm_pre<128, 1, true><<<dim3(gb, 2), 256, SMEM>>>(
        eh, el, wh + 131072, wl + 131072, invb, nullptr, (float*)d_out,
        nullptr, nullptr, nullptr, nullptr, n, 256);
}

// round 5
// speedup vs baseline: 1.7422x; 1.0680x over previous
#include <cuda_runtime.h>
#include <cuda_bf16.h>
#include <cuda_fp16.h>
#include <mma.h>
#include <math.h>
#include <stdint.h>

using namespace nvcuda;

#define NMAX 50000
#define EMAX 800000
#define DDIM 128

// ---------------- device scratch (no allocations allowed) ----------------
__device__ float g_emb [NMAX * DDIM];
__device__ float g_emb2[NMAX * DDIM];
__device__ float g_Q   [NMAX * DDIM];
__device__ __half g_KV [NMAX * 256];    // packed: [node][32 groups][k0..k3, v0..v3]
__device__ int   g_deg [NMAX];
__device__ int   g_cur [NMAX];
__device__ int   g_off [NMAX + 1];
__device__ int   g_col [EMAX];
__device__ int   g_hiOr;
// transposed bf16 weights (hi/lo): Wt[m][k] = W[k][m]
__device__ __nv_bfloat16 g_wh[163840];
__device__ __nv_bfloat16 g_wl[163840];
// pre-converted activations (hi/lo)
__device__ __nv_bfloat16 g_xh[NMAX * 256];
__device__ __nv_bfloat16 g_xl[NMAX * 256];
__device__ __nv_bfloat16 g_eh[NMAX * DDIM];
__device__ __nv_bfloat16 g_el[NMAX * DDIM];

// ---------------- CSR build kernels ----------------
__global__ void detect_kernel(const unsigned int* __restrict__ p, int E, int* hiOr)
{
    int i = blockIdx.x * blockDim.x + threadIdx.x;
    int S = (E < 4096) ? E : 4096;
    if (i < S) {
        if (p[2 * i + 1] != 0u) atomicOr(hiOr, 1);
    }
}

__device__ __forceinline__ int eidx_at(const void* p, int i, bool i64)
{
    if (i64) return (int)(((const long long*)p)[i]);
    return ((const int*)p)[i];
}

__global__ void hist_kernel(const void* __restrict__ ei, int E, int n,
                            int* __restrict__ deg, const int* __restrict__ hiOr)
{
    bool i64 = (*hiOr == 0);
    int e = blockIdx.x * blockDim.x + threadIdx.x;
    if (e < E) {
        int r = eidx_at(ei, e, i64);
        if ((unsigned)r < (unsigned)n) atomicAdd(&deg[r], 1);
    }
}

__global__ void scan_kernel(const int* __restrict__ deg, int* __restrict__ off, int n)
{
    __shared__ int warpTot[32];
    const int tid = threadIdx.x;
    const int lane = tid & 31, wid = tid >> 5;
    int carry = 0;
    for (int base = 0; base < n; base += 4096) {
        int i0 = base + tid * 4;
        int v0 = (i0     < n) ? deg[i0]     : 0;
        int v1 = (i0 + 1 < n) ? deg[i0 + 1] : 0;
        int v2 = (i0 + 2 < n) ? deg[i0 + 2] : 0;
        int v3 = (i0 + 3 < n) ? deg[i0 + 3] : 0;
        int s = v0 + v1 + v2 + v3;
        int x = s;
        #pragma unroll
        for (int o = 1; o < 32; o <<= 1) {
            int t = __shfl_up_sync(0xffffffffu, x, o);
            if (lane >= o) x += t;
        }
        if (lane == 31) warpTot[wid] = x;
        __syncthreads();
        if (wid == 0) {
            int y = warpTot[lane];
            #pragma unroll
            for (int o = 1; o < 32; o <<= 1) {
                int t = __shfl_up_sync(0xffffffffu, y, o);
                if (lane >= o) y += t;
            }
            warpTot[lane] = y;
        }
        __syncthreads();
        int wp = (wid == 0) ? 0 : warpTot[wid - 1];
        int excl = carry + wp + x - s;
        if (i0     < n) off[i0]     = excl;
        if (i0 + 1 < n) off[i0 + 1] = excl + v0;
        if (i0 + 2 < n) off[i0 + 2] = excl + v0 + v1;
        if (i0 + 3 < n) off[i0 + 3] = excl + v0 + v1 + v2;
        carry += warpTot[31];
        __syncthreads();
    }
    if (tid == 0) off[n] = carry;
}

__global__ void scatter_kernel(const void* __restrict__ ei, int E, int n,
                               const int* __restrict__ off, int* __restrict__ cur,
                               int* __restrict__ col, const int* __restrict__ hiOr)
{
    bool i64 = (*hiOr == 0);
    int e = blockIdx.x * blockDim.x + threadIdx.x;
    if (e < E) {
        int r = eidx_at(ei, e, i64);
        int c = eidx_at(ei, E + e, i64);
        if ((unsigned)r < (unsigned)n) {
            int pos = off[r] + atomicAdd(&cur[r], 1);
            if ((unsigned)c >= (unsigned)n) c = 0;
            col[pos] = c;
        }
    }
}

// ---------------- weight prep: fp32 W[K,M] -> bf16 hi/lo Wt[M,K] ----------
__global__ void prep_weights(const float* __restrict__ Wp,
                             const float* __restrict__ q1, const float* __restrict__ k1,
                             const float* __restrict__ v1,
                             const float* __restrict__ q2, const float* __restrict__ k2,
                             const float* __restrict__ v2,
                             const float* __restrict__ invw,
                             __nv_bfloat16* __restrict__ wh, __nv_bfloat16* __restrict__ wl)
{
    int idx = blockIdx.x * blockDim.x + threadIdx.x;
    if (idx >= 163840) return;
    const float* src;
    int base, M, K;
    if (idx < 32768)       { src = Wp;   base = 0;      M = 128; K = 256; }
    else if (idx < 131072) {
        int m = (idx - 32768) / 16384;
        const float* arr[6] = {q1, k1, v1, q2, k2, v2};
        src = arr[m]; base = 32768 + m * 16384; M = 128; K = 128;
    }
    else                   { src = invw; base = 131072; M = 256; K = 128; }
    int e = idx - base;
    int m = e / K, k = e - m * K;          // dst index (m, k)
    float v = src[(size_t)k * M + m];
    __nv_bfloat16 hi = __float2bfloat16(v);
    float lo = v - __bfloat162float(hi);
    wh[idx] = hi;
    wl[idx] = __float2bfloat16(lo);
}

// ---------------- activation pre-convert: fp32 -> bf16 hi/lo --------------
__device__ __forceinline__ void split4(float4 v, uint2& hv, uint2& lv)
{
    __nv_bfloat16 hx = __float2bfloat16(v.x);
    __nv_bfloat16 hy = __float2bfloat16(v.y);
    __nv_bfloat16 hz = __float2bfloat16(v.z);
    __nv_bfloat16 hw = __float2bfloat16(v.w);
    __nv_bfloat16 lx = __float2bfloat16(v.x - __bfloat162float(hx));
    __nv_bfloat16 ly = __float2bfloat16(v.y - __bfloat162float(hy));
    __nv_bfloat16 lz = __float2bfloat16(v.z - __bfloat162float(hz));
    __nv_bfloat16 lw = __float2bfloat16(v.w - __bfloat162float(hw));
    hv.x = ((uint32_t)__bfloat16_as_ushort(hy) << 16) | __bfloat16_as_ushort(hx);
    hv.y = ((uint32_t)__bfloat16_as_ushort(hw) << 16) | __bfloat16_as_ushort(hz);
    lv.x = ((uint32_t)__bfloat16_as_ushort(ly) << 16) | __bfloat16_as_ushort(lx);
    lv.y = ((uint32_t)__bfloat16_as_ushort(lw) << 16) | __bfloat16_as_ushort(lz);
}

__global__ void conv_x_kernel(const float* __restrict__ A,
                              __nv_bfloat16* __restrict__ oh, __nv_bfloat16* __restrict__ ol,
                              int total4)
{
    int i = blockIdx.x * blockDim.x + threadIdx.x;
    if (i >= total4) return;
    float4 v = *(const float4*)(A + (size_t)i * 4);
    uint2 hv, lv;
    split4(v, hv, lv);
    *(uint2*)(oh + (size_t)i * 4) = hv;
    *(uint2*)(ol + (size_t)i * 4) = lv;
}

// ---------------- WMMA bf16 hi/lo GEMM (pre-converted A) ------------------
// For o in [0,NOUT): C_o = A @ W_o. If KVPACK: o=0 -> fp32 Q, o=1/2 -> packed
// fp16 KV buffer ([node][32 groups][k4|v4]).
template <int K, int NOUT, bool BIAS, bool KVPACK>
__global__ void __launch_bounds__(256)
gemm_pre(const __nv_bfloat16* __restrict__ Ah, const __nv_bfloat16* __restrict__ Al,
         const __nv_bfloat16* __restrict__ Wth, const __nv_bfloat16* __restrict__ Wtl,
         const float* __restrict__ b1, const float* __restrict__ b2,
         float* __restrict__ C0, __half* __restrict__ kvout,
         __nv_bfloat16* __restrict__ oh, __nv_bfloat16* __restrict__ ol,
         int n, int mout)
{
    constexpr int KC  = 64;
    constexpr int LDA = KC + 8;
    constexpr int NKC = K / KC;
    constexpr int WSTRIDE = K * 128;
    extern __shared__ __align__(16) char smem[];
    __nv_bfloat16* sAh = (__nv_bfloat16*)smem;
    __nv_bfloat16* sAl = sAh + 128 * LDA;
    __nv_bfloat16* sWh = sAl + 128 * LDA;
    __nv_bfloat16* sWl = sWh + 128 * LDA;

    const int tid = threadIdx.x;
    const int warp = tid >> 5;
    const int wr = warp >> 1;
    const int wc = warp & 1;
    const int rowBase = blockIdx.x * 128;
    const int colBase = blockIdx.y * 128;

    #pragma unroll
    for (int o = 0; o < NOUT; o++) {
        wmma::fragment<wmma::accumulator, 16, 16, 16, float> acc[2][4];
        #pragma unroll
        for (int i = 0; i < 2; i++)
            #pragma unroll
            for (int j = 0; j < 4; j++) wmma::fill_fragment(acc[i][j], 0.0f);

        const __nv_bfloat16* Wh_o = Wth + (size_t)o * WSTRIDE;
        const __nv_bfloat16* Wl_o = Wtl + (size_t)o * WSTRIDE;

        for (int kc = 0; kc < NKC; kc++) {
            const int k0 = kc * KC;
            #pragma unroll
            for (int it = 0; it < 4; it++) {
                int idx = tid + it * 256;
                int r = idx >> 3, c8 = (idx & 7) * 8;
                int row = rowBase + r;
                uint4 hv = make_uint4(0u, 0u, 0u, 0u), lv = hv;
                if (row < n) {
                    size_t g = (size_t)row * K + k0 + c8;
                    hv = *(const uint4*)(Ah + g);
                    lv = *(const uint4*)(Al + g);
                }
                *(uint4*)(sAh + r * LDA + c8) = hv;
                *(uint4*)(sAl + r * LDA + c8) = lv;
            }
            #pragma unroll
            for (int it = 0; it < 4; it++) {
                int idx = tid + it * 256;
                int r = idx >> 3, c8 = (idx & 7) * 8;
                size_t g = (size_t)(colBase + r) * K + k0 + c8;
                *(uint4*)(sWh + r * LDA + c8) = *(const uint4*)(Wh_o + g);
                *(uint4*)(sWl + r * LDA + c8) = *(const uint4*)(Wl_o + g);
            }
            __syncthreads();

            #pragma unroll
            for (int ks = 0; ks < KC / 16; ks++) {
                wmma::fragment<wmma::matrix_a, 16, 16, 16, __nv_bfloat16, wmma::row_major> ah[2], al[2];
                wmma::fragment<wmma::matrix_b, 16, 16, 16, __nv_bfloat16, wmma::col_major> bh[4], bl[4];
                #pragma unroll
                for (int i = 0; i < 2; i++) {
                    const __nv_bfloat16* p = sAh + (wr * 32 + i * 16) * LDA + ks * 16;
                    wmma::load_matrix_sync(ah[i], p, LDA);
                    wmma::load_matrix_sync(al[i], p + 128 * LDA, LDA);
                }
                #pragma unroll
                for (int j = 0; j < 4; j++) {
                    const __nv_bfloat16* p = sWh + (wc * 64 + j * 16) * LDA + ks * 16;
                    wmma::load_matrix_sync(bh[j], p, LDA);
                    wmma::load_matrix_sync(bl[j], p + 128 * LDA, LDA);
                }
                #pragma unroll
                for (int i = 0; i < 2; i++)
                    #pragma unroll
                    for (int j = 0; j < 4; j++) {
                        wmma::mma_sync(acc[i][j], ah[i], bh[j], acc[i][j]);
                        wmma::mma_sync(acc[i][j], ah[i], bl[j], acc[i][j]);
                        wmma::mma_sync(acc[i][j], al[i], bh[j], acc[i][j]);
                    }
            }
            __syncthreads();
        }

        float* sC = (float*)smem;                    // 128 x 132
        #pragma unroll
        for (int i = 0; i < 2; i++)
            #pragma unroll
            for (int j = 0; j < 4; j++)
                wmma::store_matrix_sync(sC + (wr * 32 + i * 16) * 132 + wc * 64 + j * 16,
                                        acc[i][j], 132, wmma::mem_row_major);
        __syncthreads();
        #pragma unroll
        for (int it = 0; it < 16; it++) {
            int idx = tid + it * 256;
            int r = idx >> 5, c4 = (idx & 31) * 4;
            int row = rowBase + r;
            if (row < n) {
                float4 v = *(float4*)(sC + r * 132 + c4);
                if (BIAS) {
                    int col = colBase + c4;
                    v.x += b1[col];     v.y += b1[col + 1];
                    v.z += b1[col + 2]; v.w += b1[col + 3];
                    if (b2) {
                        v.x += b2[col];     v.y += b2[col + 1];
                        v.z += b2[col + 2]; v.w += b2[col + 3];
                    }
                }
                if (KVPACK && o > 0) {
                    // packed fp16: group = c4/4, K at +0, V at +4
                    __half2 h01 = __floats2half2_rn(v.x, v.y);
                    __half2 h23 = __floats2half2_rn(v.z, v.w);
                    uint2 st;
                    st.x = *(uint32_t*)&h01;
                    st.y = *(uint32_t*)&h23;
                    *(uint2*)(kvout + (size_t)row * 256 + (c4 >> 2) * 8 + ((o == 1) ? 0 : 4)) = st;
                } else {
                    size_t g = (size_t)row * mout + colBase + c4;
                    *(float4*)(C0 + g) = v;
                    if (oh) {
                        uint2 hv, lv;
                        split4(v, hv, lv);
                        *(uint2*)(oh + g) = hv;
                        *(uint2*)(ol + g) = lv;
                    }
                }
            }
        }
        __syncthreads();
    }
}

// ---------------- warp-per-node: attention agg + residual + LayerNorm ----
// KV packed fp16: one uint4 per lane per edge = k4 + v4 for this lane's dims.
__launch_bounds__(256)
__global__ void agg_ln_kernel(const float* __restrict__ Q, const __half* __restrict__ KV,
                              const float* __restrict__ emb,
                              const int* __restrict__ off, const int* __restrict__ colArr,
                              const float* __restrict__ lns, const float* __restrict__ lnb,
                              float* __restrict__ outp,
                              __nv_bfloat16* __restrict__ oh, __nv_bfloat16* __restrict__ ol,
                              int n)
{
    int gw = (blockIdx.x * blockDim.x + threadIdx.x) >> 5;   // node id
    int lane = threadIdx.x & 31;
    if (gw >= n) return;
    const int base = gw * DDIM + lane * 4;

    const float4 q4 = *(const float4*)(Q + base);
    float4 acc = make_float4(0.f, 0.f, 0.f, 0.f);
    float den = 0.f;

    int s = off[gw], e = off[gw + 1];
    int c = (s < e) ? colArr[s] : 0;
    for (int i = s; i < e; i++) {
        int cn = (i + 1 < e) ? colArr[i + 1] : 0;
        const uint4 kv = *(const uint4*)(KV + (size_t)c * 256 + lane * 8);
        __half2 k01 = *(const __half2*)&kv.x;
        __half2 k23 = *(const __half2*)&kv.y;
        __half2 v01 = *(const __half2*)&kv.z;
        __half2 v23 = *(const __half2*)&kv.w;
        float2 kf0 = __half22float2(k01);
        float2 kf1 = __half22float2(k23);
        float2 vf0 = __half22float2(v01);
        float2 vf1 = __half22float2(v23);
        float d = q4.x * kf0.x;
        d = fmaf(q4.y, kf0.y, d);
        d = fmaf(q4.z, kf1.x, d);
        d = fmaf(q4.w, kf1.y, d);
        d += __shfl_xor_sync(0xffffffffu, d, 1);
        d += __shfl_xor_sync(0xffffffffu, d, 2);
        d = fminf(10.f, fmaxf(-10.f, d));
        float w = __expf(d);
        den += w;
        acc.x = fmaf(w, vf0.x, acc.x);
        acc.y = fmaf(w, vf0.y, acc.y);
        acc.z = fmaf(w, vf1.x, acc.z);
        acc.w = fmaf(w, vf1.y, acc.w);
        c = cn;
    }

    float inv = 1.f / (den + 1e-8f);
    float4 r = *(const float4*)(emb + base);
    r.x = fmaf(acc.x, inv, r.x);
    r.y = fmaf(acc.y, inv, r.y);
    r.z = fmaf(acc.z, inv, r.z);
    r.w = fmaf(acc.w, inv, r.w);

    float ss = r.x + r.y + r.z + r.w;
    #pragma unroll
    for (int o = 16; o; o >>= 1) ss += __shfl_xor_sync(0xffffffffu, ss, o);
    float mu = ss * (1.f / 128.f);

    float dx = r.x - mu, dy = r.y - mu, dz = r.z - mu, dw = r.w - mu;
    float vs = dx * dx + dy * dy + dz * dz + dw * dw;
    #pragma unroll
    for (int o = 16; o; o >>= 1) vs += __shfl_xor_sync(0xffffffffu, vs, o);
    float var = vs * (1.f / 128.f);
    float rstd = rsqrtf(var + 1e-6f);

    const float4 s4 = *(const float4*)(lns + lane * 4);
    const float4 b4 = *(const float4*)(lnb + lane * 4);
    float4 o4;
    o4.x = dx * rstd * s4.x + b4.x;
    o4.y = dy * rstd * s4.y + b4.y;
    o4.z = dz * rstd * s4.z + b4.z;
    o4.w = dw * rstd * s4.w + b4.w;
    *(float4*)(outp + base) = o4;
    uint2 hv, lv;
    split4(o4, hv, lv);
    *(uint2*)(oh + base) = hv;
    *(uint2*)(ol + base) = lv;
}

// ---------------- launch ----------------
extern "C" void kernel_launch(void* const* d_in, const int* in_sizes, int n_in,
                              void* d_out, int out_size)
{
    const float* x    = (const float*)d_in[0];
    const void*  ei   = d_in[1];
    const float* Wp   = (const float*)d_in[2];
    const float* Wpb  = (const float*)d_in[3];
    const float* Wpos = (const float*)d_in[4];
    const float* q1   = (const float*)d_in[5];
    const float* k1   = (const float*)d_in[6];
    const float* v1   = (const float*)d_in[7];
    const float* l1s  = (const float*)d_in[8];
    const float* l1b  = (const float*)d_in[9];
    const float* q2   = (const float*)d_in[10];
    const float* k2   = (const float*)d_in[11];
    const float* v2   = (const float*)d_in[12];
    const float* l2s  = (const float*)d_in[13];
    const float* l2b  = (const float*)d_in[14];
    const float* invw = (const float*)d_in[15];
    const float* invb = (const float*)d_in[16];

    const int D   = in_sizes[3];            // 128
    const int GIN = in_sizes[2] / D;        // 256
    int n = in_sizes[0] / GIN;              // 50000
    int E = in_sizes[1] / 2;                // 800000
    if (n > NMAX) n = NMAX;
    if (E > EMAX) E = EMAX;
    (void)D; (void)n_in; (void)out_size;

    float *emb, *emb2, *Qb;
    __half *kv;
    int *deg, *cur, *off, *col, *hiOr;
    __nv_bfloat16 *wh, *wl, *xh, *xl, *eh, *el;
    cudaGetSymbolAddress((void**)&emb,  g_emb);
    cudaGetSymbolAddress((void**)&emb2, g_emb2);
    cudaGetSymbolAddress((void**)&Qb,   g_Q);
    cudaGetSymbolAddress((void**)&kv,   g_KV);
    cudaGetSymbolAddress((void**)&deg,  g_deg);
    cudaGetSymbolAddress((void**)&cur,  g_cur);
    cudaGetSymbolAddress((void**)&off,  g_off);
    cudaGetSymbolAddress((void**)&col,  g_col);
    cudaGetSymbolAddress((void**)&hiOr, g_hiOr);
    cudaGetSymbolAddress((void**)&wh,   g_wh);
    cudaGetSymbolAddress((void**)&wl,   g_wl);
    cudaGetSymbolAddress((void**)&xh,   g_xh);
    cudaGetSymbolAddress((void**)&xl,   g_xl);
    cudaGetSymbolAddress((void**)&eh,   g_eh);
    cudaGetSymbolAddress((void**)&el,   g_el);

    const int SMEM = 4 * 128 * 72 * 2;      // 73728 bytes
    cudaFuncSetAttribute(gemm_pre<256, 1, true, false>,
                         cudaFuncAttributeMaxDynamicSharedMemorySize, SMEM);
    cudaFuncSetAttribute(gemm_pre<128, 3, false, true>,
                         cudaFuncAttributeMaxDynamicSharedMemorySize, SMEM);
    cudaFuncSetAttribute(gemm_pre<128, 1, true, false>,
                         cudaFuncAttributeMaxDynamicSharedMemorySize, SMEM);

    const int eb  = (E + 255) / 256;
    const int gb  = (n + 127) / 128;
    const int ab  = (n + 7) / 8;

    // CSR build
    cudaMemsetAsync(deg, 0, (size_t)n * sizeof(int));
    cudaMemsetAsync(cur, 0, (size_t)n * sizeof(int));
    cudaMemsetAsync(hiOr, 0, sizeof(int));
    detect_kernel<<<16, 256>>>((const unsigned int*)ei, E, hiOr);
    hist_kernel<<<eb, 256>>>(ei, E, n, deg, hiOr);
    scan_kernel<<<1, 1024>>>(deg, off, n);
    scatter_kernel<<<eb, 256>>>(ei, E, n, off, cur, col, hiOr);

    // weight prep + x pre-convert
    prep_weights<<<640, 256>>>(Wp, q1, k1, v1, q2, k2, v2, invw, wh, wl);
    const int xq = n * GIN / 4;
    conv_x_kernel<<<(xq + 255) / 256, 256>>>(x, xh, xl, xq);

    // input projection + bias + positional embedding (emits emb fp32 + hi/lo)
    gemm_pre<256, 1, true, false><<<dim3(gb, 1), 256, SMEM>>>(
        xh, xl, wh, wl, Wpb, Wpos, emb, nullptr, eh, el, n, 128);

    // layer 1: fused QKV (Q fp32 + packed fp16 KV), then aggregate+LN
    gemm_pre<128, 3, false, true><<<dim3(gb, 1), 256, SMEM>>>(
        eh, el, wh + 32768, wl + 32768, nullptr, nullptr, Qb, kv,
        nullptr, nullptr, n, 128);
    agg_ln_kernel<<<ab, 256>>>(Qb, kv, emb, off, col, l1s, l1b, emb2, eh, el, n);

    // layer 2
    gemm_pre<128, 3, false, true><<<dim3(gb, 1), 256, SMEM>>>(
        eh, el, wh + 81920, wl + 81920, nullptr, nullptr, Qb, kv,
        nullptr, nullptr, n, 128);
    agg_ln_kernel<<<ab, 256>>>(Qb, kv, emb2, off, col, l2s, l2b, emb, eh, el, n);

    // output projection (256 cols -> grid.y = 2)
    gemm_pre<128, 1, true, false><<<dim3(gb, 2), 256, SMEM>>>(
        eh, el, wh + 131072, wl + 131072, invb, nullptr, (float*)d_out,
        nullptr, nullptr, nullptr, n, 256);
}

// round 6
// speedup vs baseline: 1.8718x; 1.0744x over previous
#include <cuda_runtime.h>
#include <cuda_bf16.h>
#include <cuda_fp16.h>
#include <mma.h>
#include <math.h>
#include <stdint.h>

using namespace nvcuda;

#define NMAX 50000
#define EMAX 800000
#define DDIM 128

// ---------------- device scratch (no allocations allowed) ----------------
__device__ float g_emb [NMAX * DDIM];
__device__ float g_emb2[NMAX * DDIM];
__device__ float g_Q   [NMAX * DDIM];
__device__ __half g_KV [NMAX * 256];    // packed: [node][32 groups][k0..k3, v0..v3]
__device__ int   g_deg [NMAX];
__device__ int   g_cur [NMAX];
__device__ int   g_off [NMAX + 1];
__device__ int   g_col [EMAX];
__device__ int   g_hiOr;
// transposed bf16 weights (hi/lo): Wt[m][k] = W[k][m]
__device__ __nv_bfloat16 g_wh[163840];
__device__ __nv_bfloat16 g_wl[163840];
// pre-converted activations (hi/lo)
__device__ __nv_bfloat16 g_xh[NMAX * 256];
__device__ __nv_bfloat16 g_xl[NMAX * 256];
__device__ __nv_bfloat16 g_eh[NMAX * DDIM];
__device__ __nv_bfloat16 g_el[NMAX * DDIM];

// ---------------- CSR build kernels ----------------
__global__ void detect_kernel(const unsigned int* __restrict__ p, int E, int* hiOr)
{
    int i = blockIdx.x * blockDim.x + threadIdx.x;
    int S = (E < 4096) ? E : 4096;
    if (i < S) {
        if (p[2 * i + 1] != 0u) atomicOr(hiOr, 1);
    }
}

__device__ __forceinline__ int eidx_at(const void* p, int i, bool i64)
{
    if (i64) return (int)(((const long long*)p)[i]);
    return ((const int*)p)[i];
}

__global__ void hist_kernel(const void* __restrict__ ei, int E, int n,
                            int* __restrict__ deg, const int* __restrict__ hiOr)
{
    bool i64 = (*hiOr == 0);
    int e = blockIdx.x * blockDim.x + threadIdx.x;
    if (e < E) {
        int r = eidx_at(ei, e, i64);
        if ((unsigned)r < (unsigned)n) atomicAdd(&deg[r], 1);
    }
}

__global__ void scan_kernel(const int* __restrict__ deg, int* __restrict__ off, int n)
{
    __shared__ int warpTot[32];
    const int tid = threadIdx.x;
    const int lane = tid & 31, wid = tid >> 5;
    int carry = 0;
    for (int base = 0; base < n; base += 4096) {
        int i0 = base + tid * 4;
        int v0 = (i0     < n) ? deg[i0]     : 0;
        int v1 = (i0 + 1 < n) ? deg[i0 + 1] : 0;
        int v2 = (i0 + 2 < n) ? deg[i0 + 2] : 0;
        int v3 = (i0 + 3 < n) ? deg[i0 + 3] : 0;
        int s = v0 + v1 + v2 + v3;
        int x = s;
        #pragma unroll
        for (int o = 1; o < 32; o <<= 1) {
            int t = __shfl_up_sync(0xffffffffu, x, o);
            if (lane >= o) x += t;
        }
        if (lane == 31) warpTot[wid] = x;
        __syncthreads();
        if (wid == 0) {
            int y = warpTot[lane];
            #pragma unroll
            for (int o = 1; o < 32; o <<= 1) {
                int t = __shfl_up_sync(0xffffffffu, y, o);
                if (lane >= o) y += t;
            }
            warpTot[lane] = y;
        }
        __syncthreads();
        int wp = (wid == 0) ? 0 : warpTot[wid - 1];
        int excl = carry + wp + x - s;
        if (i0     < n) off[i0]     = excl;
        if (i0 + 1 < n) off[i0 + 1] = excl + v0;
        if (i0 + 2 < n) off[i0 + 2] = excl + v0 + v1;
        if (i0 + 3 < n) off[i0 + 3] = excl + v0 + v1 + v2;
        carry += warpTot[31];
        __syncthreads();
    }
    if (tid == 0) off[n] = carry;
}

__global__ void scatter_kernel(const void* __restrict__ ei, int E, int n,
                               const int* __restrict__ off, int* __restrict__ cur,
                               int* __restrict__ col, const int* __restrict__ hiOr)
{
    bool i64 = (*hiOr == 0);
    int e = blockIdx.x * blockDim.x + threadIdx.x;
    if (e < E) {
        int r = eidx_at(ei, e, i64);
        int c = eidx_at(ei, E + e, i64);
        if ((unsigned)r < (unsigned)n) {
            int pos = off[r] + atomicAdd(&cur[r], 1);
            if ((unsigned)c >= (unsigned)n) c = 0;
            col[pos] = c;
        }
    }
}

// ---------------- weight prep: fp32 W[K,M] -> bf16 hi/lo Wt[M,K] ----------
__global__ void prep_weights(const float* __restrict__ Wp,
                             const float* __restrict__ q1, const float* __restrict__ k1,
                             const float* __restrict__ v1,
                             const float* __restrict__ q2, const float* __restrict__ k2,
                             const float* __restrict__ v2,
                             const float* __restrict__ invw,
                             __nv_bfloat16* __restrict__ wh, __nv_bfloat16* __restrict__ wl)
{
    int idx = blockIdx.x * blockDim.x + threadIdx.x;
    if (idx >= 163840) return;
    const float* src;
    int base, M, K;
    if (idx < 32768)       { src = Wp;   base = 0;      M = 128; K = 256; }
    else if (idx < 131072) {
        int m = (idx - 32768) / 16384;
        const float* arr[6] = {q1, k1, v1, q2, k2, v2};
        src = arr[m]; base = 32768 + m * 16384; M = 128; K = 128;
    }
    else                   { src = invw; base = 131072; M = 256; K = 128; }
    int e = idx - base;
    int m = e / K, k = e - m * K;          // dst index (m, k)
    float v = src[(size_t)k * M + m];
    __nv_bfloat16 hi = __float2bfloat16(v);
    float lo = v - __bfloat162float(hi);
    wh[idx] = hi;
    wl[idx] = __float2bfloat16(lo);
}

// ---------------- activation pre-convert: fp32 -> bf16 hi/lo --------------
__device__ __forceinline__ void split4(float4 v, uint2& hv, uint2& lv)
{
    __nv_bfloat16 hx = __float2bfloat16(v.x);
    __nv_bfloat16 hy = __float2bfloat16(v.y);
    __nv_bfloat16 hz = __float2bfloat16(v.z);
    __nv_bfloat16 hw = __float2bfloat16(v.w);
    __nv_bfloat16 lx = __float2bfloat16(v.x - __bfloat162float(hx));
    __nv_bfloat16 ly = __float2bfloat16(v.y - __bfloat162float(hy));
    __nv_bfloat16 lz = __float2bfloat16(v.z - __bfloat162float(hz));
    __nv_bfloat16 lw = __float2bfloat16(v.w - __bfloat162float(hw));
    hv.x = ((uint32_t)__bfloat16_as_ushort(hy) << 16) | __bfloat16_as_ushort(hx);
    hv.y = ((uint32_t)__bfloat16_as_ushort(hw) << 16) | __bfloat16_as_ushort(hz);
    lv.x = ((uint32_t)__bfloat16_as_ushort(ly) << 16) | __bfloat16_as_ushort(lx);
    lv.y = ((uint32_t)__bfloat16_as_ushort(lw) << 16) | __bfloat16_as_ushort(lz);
}

__global__ void conv_x_kernel(const float* __restrict__ A,
                              __nv_bfloat16* __restrict__ oh, __nv_bfloat16* __restrict__ ol,
                              int total4)
{
    int i = blockIdx.x * blockDim.x + threadIdx.x;
    if (i >= total4) return;
    float4 v = *(const float4*)(A + (size_t)i * 4);
    uint2 hv, lv;
    split4(v, hv, lv);
    *(uint2*)(oh + (size_t)i * 4) = hv;
    *(uint2*)(ol + (size_t)i * 4) = lv;
}

// ---------------- generic WMMA bf16 hi/lo GEMM (KC=64 chunks) -------------
template <int K, bool BIAS>
__global__ void __launch_bounds__(256)
gemm_pre(const __nv_bfloat16* __restrict__ Ah, const __nv_bfloat16* __restrict__ Al,
         const __nv_bfloat16* __restrict__ Wth, const __nv_bfloat16* __restrict__ Wtl,
         const float* __restrict__ b1, const float* __restrict__ b2,
         float* __restrict__ C0,
         __nv_bfloat16* __restrict__ oh, __nv_bfloat16* __restrict__ ol,
         int n, int mout)
{
    constexpr int KC  = 64;
    constexpr int LDA = KC + 8;
    constexpr int NKC = K / KC;
    extern __shared__ __align__(16) char smem[];
    __nv_bfloat16* sAh = (__nv_bfloat16*)smem;
    __nv_bfloat16* sAl = sAh + 128 * LDA;
    __nv_bfloat16* sWh = sAl + 128 * LDA;
    __nv_bfloat16* sWl = sWh + 128 * LDA;

    const int tid = threadIdx.x;
    const int warp = tid >> 5;
    const int wr = warp >> 1;
    const int wc = warp & 1;
    const int rowBase = blockIdx.x * 128;
    const int colBase = blockIdx.y * 128;

    wmma::fragment<wmma::accumulator, 16, 16, 16, float> acc[2][4];
    #pragma unroll
    for (int i = 0; i < 2; i++)
        #pragma unroll
        for (int j = 0; j < 4; j++) wmma::fill_fragment(acc[i][j], 0.0f);

    for (int kc = 0; kc < NKC; kc++) {
        const int k0 = kc * KC;
        #pragma unroll
        for (int it = 0; it < 4; it++) {
            int idx = tid + it * 256;
            int r = idx >> 3, c8 = (idx & 7) * 8;
            int row = rowBase + r;
            uint4 hv = make_uint4(0u, 0u, 0u, 0u), lv = hv;
            if (row < n) {
                size_t g = (size_t)row * K + k0 + c8;
                hv = *(const uint4*)(Ah + g);
                lv = *(const uint4*)(Al + g);
            }
            *(uint4*)(sAh + r * LDA + c8) = hv;
            *(uint4*)(sAl + r * LDA + c8) = lv;
        }
        #pragma unroll
        for (int it = 0; it < 4; it++) {
            int idx = tid + it * 256;
            int r = idx >> 3, c8 = (idx & 7) * 8;
            size_t g = (size_t)(colBase + r) * K + k0 + c8;
            *(uint4*)(sWh + r * LDA + c8) = *(const uint4*)(Wth + g);
            *(uint4*)(sWl + r * LDA + c8) = *(const uint4*)(Wtl + g);
        }
        __syncthreads();

        #pragma unroll
        for (int ks = 0; ks < KC / 16; ks++) {
            wmma::fragment<wmma::matrix_a, 16, 16, 16, __nv_bfloat16, wmma::row_major> ah[2], al[2];
            wmma::fragment<wmma::matrix_b, 16, 16, 16, __nv_bfloat16, wmma::col_major> bh[4], bl[4];
            #pragma unroll
            for (int i = 0; i < 2; i++) {
                const __nv_bfloat16* p = sAh + (wr * 32 + i * 16) * LDA + ks * 16;
                wmma::load_matrix_sync(ah[i], p, LDA);
                wmma::load_matrix_sync(al[i], p + 128 * LDA, LDA);
            }
            #pragma unroll
            for (int j = 0; j < 4; j++) {
                const __nv_bfloat16* p = sWh + (wc * 64 + j * 16) * LDA + ks * 16;
                wmma::load_matrix_sync(bh[j], p, LDA);
                wmma::load_matrix_sync(bl[j], p + 128 * LDA, LDA);
            }
            #pragma unroll
            for (int i = 0; i < 2; i++)
                #pragma unroll
                for (int j = 0; j < 4; j++) {
                    wmma::mma_sync(acc[i][j], ah[i], bh[j], acc[i][j]);
                    wmma::mma_sync(acc[i][j], ah[i], bl[j], acc[i][j]);
                    wmma::mma_sync(acc[i][j], al[i], bh[j], acc[i][j]);
                }
        }
        __syncthreads();
    }

    float* sC = (float*)smem;                    // 128 x 132
    #pragma unroll
    for (int i = 0; i < 2; i++)
        #pragma unroll
        for (int j = 0; j < 4; j++)
            wmma::store_matrix_sync(sC + (wr * 32 + i * 16) * 132 + wc * 64 + j * 16,
                                    acc[i][j], 132, wmma::mem_row_major);
    __syncthreads();
    #pragma unroll
    for (int it = 0; it < 16; it++) {
        int idx = tid + it * 256;
        int r = idx >> 5, c4 = (idx & 31) * 4;
        int row = rowBase + r;
        if (row < n) {
            float4 v = *(float4*)(sC + r * 132 + c4);
            if (BIAS) {
                int col = colBase + c4;
                v.x += b1[col];     v.y += b1[col + 1];
                v.z += b1[col + 2]; v.w += b1[col + 3];
                if (b2) {
                    v.x += b2[col];     v.y += b2[col + 1];
                    v.z += b2[col + 2]; v.w += b2[col + 3];
                }
            }
            size_t g = (size_t)row * mout + colBase + c4;
            *(float4*)(C0 + g) = v;
            if (oh) {
                uint2 hv, lv;
                split4(v, hv, lv);
                *(uint2*)(oh + g) = hv;
                *(uint2*)(ol + g) = lv;
            }
        }
    }
}

// ---------------- fused QKV GEMM: A staged ONCE, W streamed per output ----
// K = 128. o=0 -> fp32 Q; o=1 (K), o=2 (V) -> packed fp16 KV.
__global__ void __launch_bounds__(256)
gemm_qkv(const __nv_bfloat16* __restrict__ Ah, const __nv_bfloat16* __restrict__ Al,
         const __nv_bfloat16* __restrict__ Wth, const __nv_bfloat16* __restrict__ Wtl,
         float* __restrict__ Qout, __half* __restrict__ kvout, int n)
{
    constexpr int K   = 128;
    constexpr int LDA = K + 8;          // 136
    extern __shared__ __align__(16) char smem[];
    __nv_bfloat16* sAh = (__nv_bfloat16*)smem;          // 128*136
    __nv_bfloat16* sAl = sAh + 128 * LDA;
    __nv_bfloat16* sWh = sAl + 128 * LDA;
    __nv_bfloat16* sWl = sWh + 128 * LDA;
    float*         sC  = (float*)sWh;                    // reuse W region (128x132 fp32)

    const int tid = threadIdx.x;
    const int warp = tid >> 5;
    const int wr = warp >> 1;
    const int wc = warp & 1;
    const int rowBase = blockIdx.x * 128;

    // stage full A (hi/lo) once
    #pragma unroll
    for (int it = 0; it < 8; it++) {
        int idx = tid + it * 256;               // 2048 uint4 per buffer
        int r = idx >> 4, c8 = (idx & 15) * 8;
        int row = rowBase + r;
        uint4 hv = make_uint4(0u, 0u, 0u, 0u), lv = hv;
        if (row < n) {
            size_t g = (size_t)row * K + c8;
            hv = *(const uint4*)(Ah + g);
            lv = *(const uint4*)(Al + g);
        }
        *(uint4*)(sAh + r * LDA + c8) = hv;
        *(uint4*)(sAl + r * LDA + c8) = lv;
    }

    for (int o = 0; o < 3; o++) {
        // stage W_o (full 128x128 hi/lo)
        const __nv_bfloat16* Wh_o = Wth + (size_t)o * (K * 128);
        const __nv_bfloat16* Wl_o = Wtl + (size_t)o * (K * 128);
        #pragma unroll
        for (int it = 0; it < 8; it++) {
            int idx = tid + it * 256;
            int r = idx >> 4, c8 = (idx & 15) * 8;
            size_t g = (size_t)r * K + c8;
            *(uint4*)(sWh + r * LDA + c8) = *(const uint4*)(Wh_o + g);
            *(uint4*)(sWl + r * LDA + c8) = *(const uint4*)(Wl_o + g);
        }
        __syncthreads();

        wmma::fragment<wmma::accumulator, 16, 16, 16, float> acc[2][4];
        #pragma unroll
        for (int i = 0; i < 2; i++)
            #pragma unroll
            for (int j = 0; j < 4; j++) wmma::fill_fragment(acc[i][j], 0.0f);

        #pragma unroll
        for (int ks = 0; ks < 8; ks++) {
            wmma::fragment<wmma::matrix_a, 16, 16, 16, __nv_bfloat16, wmma::row_major> ah[2], al[2];
            wmma::fragment<wmma::matrix_b, 16, 16, 16, __nv_bfloat16, wmma::col_major> bh[4], bl[4];
            #pragma unroll
            for (int i = 0; i < 2; i++) {
                const __nv_bfloat16* p = sAh + (wr * 32 + i * 16) * LDA + ks * 16;
                wmma::load_matrix_sync(ah[i], p, LDA);
                wmma::load_matrix_sync(al[i], p + 128 * LDA, LDA);
            }
            #pragma unroll
            for (int j = 0; j < 4; j++) {
                const __nv_bfloat16* p = sWh + (wc * 64 + j * 16) * LDA + ks * 16;
                wmma::load_matrix_sync(bh[j], p, LDA);
                wmma::load_matrix_sync(bl[j], p + 128 * LDA, LDA);
            }
            #pragma unroll
            for (int i = 0; i < 2; i++)
                #pragma unroll
                for (int j = 0; j < 4; j++) {
                    wmma::mma_sync(acc[i][j], ah[i], bh[j], acc[i][j]);
                    wmma::mma_sync(acc[i][j], ah[i], bl[j], acc[i][j]);
                    wmma::mma_sync(acc[i][j], al[i], bh[j], acc[i][j]);
                }
        }
        __syncthreads();   // all MMA reads of sW done before sC overwrite

        #pragma unroll
        for (int i = 0; i < 2; i++)
            #pragma unroll
            for (int j = 0; j < 4; j++)
                wmma::store_matrix_sync(sC + (wr * 32 + i * 16) * 132 + wc * 64 + j * 16,
                                        acc[i][j], 132, wmma::mem_row_major);
        __syncthreads();

        #pragma unroll
        for (int it = 0; it < 16; it++) {
            int idx = tid + it * 256;
            int r = idx >> 5, c4 = (idx & 31) * 4;
            int row = rowBase + r;
            if (row < n) {
                float4 v = *(float4*)(sC + r * 132 + c4);
                if (o == 0) {
                    *(float4*)(Qout + (size_t)row * 128 + c4) = v;
                } else {
                    __half2 h01 = __floats2half2_rn(v.x, v.y);
                    __half2 h23 = __floats2half2_rn(v.z, v.w);
                    uint2 st;
                    st.x = *(uint32_t*)&h01;
                    st.y = *(uint32_t*)&h23;
                    *(uint2*)(kvout + (size_t)row * 256 + (c4 >> 2) * 8 + ((o == 1) ? 0 : 4)) = st;
                }
            }
        }
        __syncthreads();   // epilogue reads of sC done before next W stage
    }
}

// ---------------- warp-per-node agg + residual + LayerNorm (MLP=4) -------
__device__ __forceinline__ void agg_edge(uint4 kv, float4 q4, float4& acc, float& den)
{
    float2 kf0 = __half22float2(*(const __half2*)&kv.x);
    float2 kf1 = __half22float2(*(const __half2*)&kv.y);
    float2 vf0 = __half22float2(*(const __half2*)&kv.z);
    float2 vf1 = __half22float2(*(const __half2*)&kv.w);
    float d = q4.x * kf0.x;
    d = fmaf(q4.y, kf0.y, d);
    d = fmaf(q4.z, kf1.x, d);
    d = fmaf(q4.w, kf1.y, d);
    d += __shfl_xor_sync(0xffffffffu, d, 1);
    d += __shfl_xor_sync(0xffffffffu, d, 2);
    d = fminf(10.f, fmaxf(-10.f, d));
    float w = __expf(d);
    den += w;
    acc.x = fmaf(w, vf0.x, acc.x);
    acc.y = fmaf(w, vf0.y, acc.y);
    acc.z = fmaf(w, vf1.x, acc.z);
    acc.w = fmaf(w, vf1.y, acc.w);
}

__launch_bounds__(256)
__global__ void agg_ln_kernel(const float* __restrict__ Q, const __half* __restrict__ KV,
                              const float* __restrict__ emb,
                              const int* __restrict__ off, const int* __restrict__ colArr,
                              const float* __restrict__ lns, const float* __restrict__ lnb,
                              float* __restrict__ outp,
                              __nv_bfloat16* __restrict__ oh, __nv_bfloat16* __restrict__ ol,
                              int n)
{
    int gw = (blockIdx.x * blockDim.x + threadIdx.x) >> 5;   // node id
    int lane = threadIdx.x & 31;
    if (gw >= n) return;
    const int base = gw * DDIM + lane * 4;
    const int koff = lane * 8;

    const float4 q4 = *(const float4*)(Q + base);
    float4 acc = make_float4(0.f, 0.f, 0.f, 0.f);
    float den = 0.f;

    int s = off[gw], e = off[gw + 1];
    int i = s;
    for (; i + 4 <= e; i += 4) {
        int c0 = colArr[i],     c1 = colArr[i + 1];
        int c2 = colArr[i + 2], c3 = colArr[i + 3];
        uint4 kv0 = *(const uint4*)(KV + (size_t)c0 * 256 + koff);
        uint4 kv1 = *(const uint4*)(KV + (size_t)c1 * 256 + koff);
        uint4 kv2 = *(const uint4*)(KV + (size_t)c2 * 256 + koff);
        uint4 kv3 = *(const uint4*)(KV + (size_t)c3 * 256 + koff);
        agg_edge(kv0, q4, acc, den);
        agg_edge(kv1, q4, acc, den);
        agg_edge(kv2, q4, acc, den);
        agg_edge(kv3, q4, acc, den);
    }
    for (; i < e; i++) {
        int c = colArr[i];
        uint4 kv = *(const uint4*)(KV + (size_t)c * 256 + koff);
        agg_edge(kv, q4, acc, den);
    }

    float inv = 1.f / (den + 1e-8f);
    float4 r = *(const float4*)(emb + base);
    r.x = fmaf(acc.x, inv, r.x);
    r.y = fmaf(acc.y, inv, r.y);
    r.z = fmaf(acc.z, inv, r.z);
    r.w = fmaf(acc.w, inv, r.w);

    float ss = r.x + r.y + r.z + r.w;
    #pragma unroll
    for (int o = 16; o; o >>= 1) ss += __shfl_xor_sync(0xffffffffu, ss, o);
    float mu = ss * (1.f / 128.f);

    float dx = r.x - mu, dy = r.y - mu, dz = r.z - mu, dw = r.w - mu;
    float vs = dx * dx + dy * dy + dz * dz + dw * dw;
    #pragma unroll
    for (int o = 16; o; o >>= 1) vs += __shfl_xor_sync(0xffffffffu, vs, o);
    float var = vs * (1.f / 128.f);
    float rstd = rsqrtf(var + 1e-6f);

    const float4 s4 = *(const float4*)(lns + lane * 4);
    const float4 b4 = *(const float4*)(lnb + lane * 4);
    float4 o4;
    o4.x = dx * rstd * s4.x + b4.x;
    o4.y = dy * rstd * s4.y + b4.y;
    o4.z = dz * rstd * s4.z + b4.z;
    o4.w = dw * rstd * s4.w + b4.w;
    *(float4*)(outp + base) = o4;
    uint2 hv, lv;
    split4(o4, hv, lv);
    *(uint2*)(oh + base) = hv;
    *(uint2*)(ol + base) = lv;
}

// ---------------- launch ----------------
extern "C" void kernel_launch(void* const* d_in, const int* in_sizes, int n_in,
                              void* d_out, int out_size)
{
    const float* x    = (const float*)d_in[0];
    const void*  ei   = d_in[1];
    const float* Wp   = (const float*)d_in[2];
    const float* Wpb  = (const float*)d_in[3];
    const float* Wpos = (const float*)d_in[4];
    const float* q1   = (const float*)d_in[5];
    const float* k1   = (const float*)d_in[6];
    const float* v1   = (const float*)d_in[7];
    const float* l1s  = (const float*)d_in[8];
    const float* l1b  = (const float*)d_in[9];
    const float* q2   = (const float*)d_in[10];
    const float* k2   = (const float*)d_in[11];
    const float* v2   = (const float*)d_in[12];
    const float* l2s  = (const float*)d_in[13];
    const float* l2b  = (const float*)d_in[14];
    const float* invw = (const float*)d_in[15];
    const float* invb = (const float*)d_in[16];

    const int D   = in_sizes[3];            // 128
    const int GIN = in_sizes[2] / D;        // 256
    int n = in_sizes[0] / GIN;              // 50000
    int E = in_sizes[1] / 2;                // 800000
    if (n > NMAX) n = NMAX;
    if (E > EMAX) E = EMAX;
    (void)D; (void)n_in; (void)out_size;

    float *emb, *emb2, *Qb;
    __half *kv;
    int *deg, *cur, *off, *col, *hiOr;
    __nv_bfloat16 *wh, *wl, *xh, *xl, *eh, *el;
    cudaGetSymbolAddress((void**)&emb,  g_emb);
    cudaGetSymbolAddress((void**)&emb2, g_emb2);
    cudaGetSymbolAddress((void**)&Qb,   g_Q);
    cudaGetSymbolAddress((void**)&kv,   g_KV);
    cudaGetSymbolAddress((void**)&deg,  g_deg);
    cudaGetSymbolAddress((void**)&cur,  g_cur);
    cudaGetSymbolAddress((void**)&off,  g_off);
    cudaGetSymbolAddress((void**)&col,  g_col);
    cudaGetSymbolAddress((void**)&hiOr, g_hiOr);
    cudaGetSymbolAddress((void**)&wh,   g_wh);
    cudaGetSymbolAddress((void**)&wl,   g_wl);
    cudaGetSymbolAddress((void**)&xh,   g_xh);
    cudaGetSymbolAddress((void**)&xl,   g_xl);
    cudaGetSymbolAddress((void**)&eh,   g_eh);
    cudaGetSymbolAddress((void**)&el,   g_el);

    const int SMEM_G = 4 * 128 * 72 * 2;    // 73728 (generic, KC=64)
    const int SMEM_Q = 4 * 128 * 136 * 2;   // 139264 (qkv, full K staged)
    cudaFuncSetAttribute(gemm_pre<256, true>,
                         cudaFuncAttributeMaxDynamicSharedMemorySize, SMEM_G);
    cudaFuncSetAttribute(gemm_pre<128, true>,
                         cudaFuncAttributeMaxDynamicSharedMemorySize, SMEM_G);
    cudaFuncSetAttribute(gemm_qkv,
                         cudaFuncAttributeMaxDynamicSharedMemorySize, SMEM_Q);

    const int eb  = (E + 255) / 256;
    const int gb  = (n + 127) / 128;
    const int ab  = (n + 7) / 8;

    // CSR build
    cudaMemsetAsync(deg, 0, (size_t)n * sizeof(int));
    cudaMemsetAsync(cur, 0, (size_t)n * sizeof(int));
    cudaMemsetAsync(hiOr, 0, sizeof(int));
    detect_kernel<<<16, 256>>>((const unsigned int*)ei, E, hiOr);
    hist_kernel<<<eb, 256>>>(ei, E, n, deg, hiOr);
    scan_kernel<<<1, 1024>>>(deg, off, n);
    scatter_kernel<<<eb, 256>>>(ei, E, n, off, cur, col, hiOr);

    // weight prep + x pre-convert
    prep_weights<<<640, 256>>>(Wp, q1, k1, v1, q2, k2, v2, invw, wh, wl);
    const int xq = n * GIN / 4;
    conv_x_kernel<<<(xq + 255) / 256, 256>>>(x, xh, xl, xq);

    // input projection + bias + positional embedding (emits emb fp32 + hi/lo)
    gemm_pre<256, true><<<dim3(gb, 1), 256, SMEM_G>>>(
        xh, xl, wh, wl, Wpb, Wpos, emb, eh, el, n, 128);

    // layer 1: fused QKV (A staged once), then aggregate+LN
    gemm_qkv<<<gb, 256, SMEM_Q>>>(eh, el, wh + 32768, wl + 32768, Qb, kv, n);
    agg_ln_kernel<<<ab, 256>>>(Qb, kv, emb, off, col, l1s, l1b, emb2, eh, el, n);

    // layer 2
    gemm_qkv<<<gb, 256, SMEM_Q>>>(eh, el, wh + 81920, wl + 81920, Qb, kv, n);
    agg_ln_kernel<<<ab, 256>>>(Qb, kv, emb2, off, col, l2s, l2b, emb, eh, el, n);

    // output projection (256 cols -> grid.y = 2)
    gemm_pre<128, true><<<dim3(gb, 2), 256, SMEM_G>>>(
        eh, el, wh + 131072, wl + 131072, invb, nullptr, (float*)d_out,
        nullptr, nullptr, n, 256);
}